// round 13
// baseline (speedup 1.0000x reference)
#include <cuda_runtime.h>
#include <cuda_bf16.h>
#include <cstdint>

#define NN 262144
#define DD 128
#define KK 512
#define GG 4096
#define TT 10

// output layout (float32, concatenated reference tuple)
#define OFF_CPRE   0
#define OFF_XPRE   (GG * TT)            // counter_pre
#define OFF_YPRE   (2 * GG * TT)
#define OFF_Z      (3 * GG * TT)
#define OFF_PCA    (OFF_Z + (size_t)NN * DD)
#define OFF_PX     (OFF_PCA + (size_t)GG * DD)

#define MARGIN_THRESH 0.01f

#define LDB 136                         // bf16 tile leading dim (elements)
#define BTILE_U4 4352                   // one code tile (bh+bl) in uint4s

// smem byte offsets (128-node CTA): [xh][xl][B0][B1][c2][merge]
#define SM_XH   0
#define SM_XL   34816
#define SM_B0   69632
#define SM_B1   139264
#define SM_C2   208896
#define SM_MG   210944                  // 3 x 2 x 128 x 4 = 3072
#define SMEM_TC 214016

__device__ int   g_idx[NN];
__device__ int   g_seg[GG + 1];
__device__ float g_c2[KK];       // fast-path c2
__device__ float g_c2e[KK];      // reference-emulated c2 (sequential fp32, no fma)
__device__ float g_cbT[DD * KK]; // transposed causal codebook for coalesced refine
__device__ int   g_flag[NN];
__device__ int   g_nflag;
__device__ uint4 g_cbs[4][BTILE_U4];   // pre-split codebook tiles: [bh | bl] blocked layout

// ---------------- asm helpers ----------------
__device__ __forceinline__ void cpa16(uint32_t saddr, const void* gptr) {
    asm volatile("cp.async.cg.shared.global [%0], [%1], 16;" :: "r"(saddr), "l"(gptr));
}
__device__ __forceinline__ void cpa_commit() { asm volatile("cp.async.commit_group;"); }
__device__ __forceinline__ void cpa_wait0() { asm volatile("cp.async.wait_group 0;"); }
__device__ __forceinline__ void cpa_wait1() { asm volatile("cp.async.wait_group 1;"); }

__device__ __forceinline__ void ldsm4(uint32_t* r, uint32_t addr) {
    asm volatile("ldmatrix.sync.aligned.m8n8.x4.shared.b16 {%0,%1,%2,%3}, [%4];"
                 : "=r"(r[0]), "=r"(r[1]), "=r"(r[2]), "=r"(r[3]) : "r"(addr));
}
__device__ __forceinline__ void mma_bf16(float* c, const uint32_t* a, const uint32_t* b) {
    asm volatile(
        "mma.sync.aligned.m16n8k16.row.col.f32.bf16.bf16.f32 "
        "{%0,%1,%2,%3}, {%4,%5,%6,%7}, {%8,%9}, {%0,%1,%2,%3};"
        : "+f"(c[0]), "+f"(c[1]), "+f"(c[2]), "+f"(c[3])
        : "r"(a[0]), "r"(a[1]), "r"(a[2]), "r"(a[3]), "r"(b[0]), "r"(b[1]));
}

// symmetric top-2 merge with first-index tie-break
__device__ __forceinline__ void comb2(float& v1, int& i1, float& v2,
                                      float ov1, int oi1, float ov2) {
    if (ov1 < v1 || (ov1 == v1 && oi1 < i1)) {
        v2 = fminf(v1, ov2);
        v1 = ov1; i1 = oi1;
    } else {
        v2 = fminf(v2, ov1);
    }
}

// split one 8-float chunk to packed bf16 hi/lo uint4s
__device__ __forceinline__ void split8(const float* f, uint4& H, uint4& L) {
    uint32_t hp[4], lp[4];
#pragma unroll
    for (int j = 0; j < 4; ++j) {
        __nv_bfloat16 h0 = __float2bfloat16(f[2 * j]);
        __nv_bfloat16 h1 = __float2bfloat16(f[2 * j + 1]);
        __nv_bfloat16 l0 = __float2bfloat16(f[2 * j]     - __bfloat162float(h0));
        __nv_bfloat16 l1 = __float2bfloat16(f[2 * j + 1] - __bfloat162float(h1));
        hp[j] = ((uint32_t)__bfloat16_as_ushort(h1) << 16) | __bfloat16_as_ushort(h0);
        lp[j] = ((uint32_t)__bfloat16_as_ushort(l1) << 16) | __bfloat16_as_ushort(l0);
    }
    H = make_uint4(hp[0], hp[1], hp[2], hp[3]);
    L = make_uint4(lp[0], lp[1], lp[2], lp[3]);
}

// ---------------- fused setup: seg (blocks 0-16) + prep (17-80) + split (81-84) ------
__global__ __launch_bounds__(256) void setup_kernel(
    const int* __restrict__ bw, const float* __restrict__ cc)
{
    const int b = blockIdx.x;
    const int tid = threadIdx.x;
    if (b < 17) {
        int g = b * 256 + tid;
        if (g == 0) g_nflag = 0;
        if (g > GG) return;
        const int n = NN;
        bool is64 = (bw[n - 1] == 0) && (bw[n - 3] == 0);
        int lo = 0, hi = n;
        while (lo < hi) {
            int mid = (lo + hi) >> 1;
            int v = is64 ? bw[2 * mid] : bw[mid];
            if (v < g) lo = mid + 1; else hi = mid;
        }
        g_seg[g] = lo;
    } else if (b < 81) {
        int k = (b - 17) * 8 + (tid >> 5);
        int lane = tid & 31;
        float v[4];
        float s = 0.f;
#pragma unroll
        for (int j = 0; j < 4; ++j) {
            v[j] = cc[k * DD + lane + 32 * j];
            s = fmaf(v[j], v[j], s);
            g_cbT[(lane + 32 * j) * KK + k] = v[j];
        }
#pragma unroll
        for (int o = 16; o; o >>= 1) s += __shfl_xor_sync(0xffffffffu, s, o);
        if (lane == 0) g_c2[k] = s;
        if (lane == 0) {
            const float* r = cc + (size_t)k * DD;
            float acc = 0.f;
            for (int d = 0; d < DD; ++d)
                acc = __fadd_rn(acc, __fmul_rn(r[d], r[d]));
            g_c2e[k] = acc;
        }
    } else {
        const int kt = b - 81;
#pragma unroll
        for (int it = 0; it < 8; ++it) {
            int idx = it * 256 + tid;
            int row = idx >> 4, ch = idx & 15;
            float f[8];
            const float4* p = (const float4*)(cc + (size_t)(kt * 128 + row) * DD) + ch * 2;
            float4 v0 = p[0], v1 = p[1];
            f[0]=v0.x; f[1]=v0.y; f[2]=v0.z; f[3]=v0.w;
            f[4]=v1.x; f[5]=v1.y; f[6]=v1.z; f[7]=v1.w;
            uint4 H, L;
            split8(f, H, L);
            int u4 = row * 17 + ch;
            g_cbs[kt][u4] = H;
            g_cbs[kt][2176 + u4] = L;
        }
    }
}

// ---------------- HMMA argmin: 128 nodes/CTA, mma.sync + in-register scan ------------
__global__ __launch_bounds__(256) void argmin_tc(const float* __restrict__ x)
{
    extern __shared__ char smem[];
    __nv_bfloat16* xh  = (__nv_bfloat16*)(smem + SM_XH);
    __nv_bfloat16* xl  = (__nv_bfloat16*)(smem + SM_XL);
    float*         c2s = (float*)(smem + SM_C2);

    const int tid  = threadIdx.x;
    const int wid  = tid >> 5;
    const int lane = tid & 31;
    const int wm   = wid & 3;            // node block: rows 32*wm..
    const int wn   = wid >> 2;           // code block: cols 64*wn..
    const int nbase = blockIdx.x * 128;
    const int g4   = lane >> 2;          // quad row id 0..7
    const int t4   = lane & 3;           // quad col id 0..3

    const uint32_t sb0 = (uint32_t)__cvta_generic_to_shared(smem + SM_B0);
    const uint32_t sb1 = (uint32_t)__cvta_generic_to_shared(smem + SM_B1);
    const uint32_t sxh = (uint32_t)__cvta_generic_to_shared(xh);
    const uint32_t sxl = (uint32_t)__cvta_generic_to_shared(xl);

    // prefetch tiles 0,1 into B0,B1 while converting X
#pragma unroll
    for (int b = 0; b < 2; ++b) {
        const uint4* src = g_cbs[b];
        uint32_t dst = b ? sb1 : sb0;
#pragma unroll
        for (int i = 0; i < 17; ++i) {
            int idx = tid + 256 * i;
            cpa16(dst + idx * 16, src + idx);
        }
        cpa_commit();
    }

    // fill X (128 rows) bf16 hi/lo
#pragma unroll
    for (int it = 0; it < 8; ++it) {
        int idx = it * 256 + tid;
        int row = idx >> 4, ch = idx & 15;
        const float4* p = (const float4*)(x + (size_t)(nbase + row) * DD) + ch * 2;
        float4 v0 = p[0], v1 = p[1];
        float f[8] = {v0.x, v0.y, v0.z, v0.w, v1.x, v1.y, v1.z, v1.w};
        uint4 H, L;
        split8(f, H, L);
        int eo = row * LDB + ch * 8;
        *(uint4*)((char*)xh + 2 * eo) = H;
        *(uint4*)((char*)xl + 2 * eo) = L;
    }
    for (int k = tid; k < KK; k += 256) c2s[k] = g_c2[k];

    // ldmatrix lane-offsets
    const int a_el = (wm * 32 + (lane & 7) + 8 * ((lane >> 3) & 1)) * LDB + 8 * (lane >> 4);
    const int b_el = (wn * 64 + (lane & 7) + 8 * (lane >> 4)) * LDB + 8 * ((lane >> 3) & 1);

    float bv[4], bv2[4];
    int   bik[4];
#pragma unroll
    for (int s = 0; s < 4; ++s) { bv[s] = 3.4e38f; bv2[s] = 3.4e38f; bik[s] = 0x7fffffff; }

    for (int kt = 0; kt < 4; ++kt) {
        if (kt == 0) cpa_wait1(); else cpa_wait0();
        __syncthreads();                 // B(kt) ready; all warps done with B(kt-1)

        if (kt < 3) {                    // prefetch kt+1 into buf((kt+1)&1) (= kt-1's)
            const uint4* src = g_cbs[kt + 1];
            uint32_t dst = ((kt + 1) & 1) ? sb1 : sb0;
#pragma unroll
            for (int i = 0; i < 17; ++i) {
                int idx = tid + 256 * i;
                cpa16(dst + idx * 16, src + idx);
            }
            cpa_commit();
        }

        const uint32_t bbh = (kt & 1) ? sb1 : sb0;
        const uint32_t bbl = bbh + 34816;

        float acc[2][8][4];
#pragma unroll
        for (int i = 0; i < 2; ++i)
#pragma unroll
            for (int j = 0; j < 8; ++j)
#pragma unroll
                for (int c = 0; c < 4; ++c) acc[i][j][c] = 0.f;

#pragma unroll
        for (int kk = 0; kk < 8; ++kk) {
            const int k0 = kk * 16;
            uint32_t ah[2][4], al[2][4], bh[8][2], bl[8][2];
#pragma unroll
            for (int i = 0; i < 2; ++i) {
                uint32_t off = (uint32_t)(a_el + i * 16 * LDB + k0) * 2;
                ldsm4(ah[i], sxh + off);
                ldsm4(al[i], sxl + off);
            }
#pragma unroll
            for (int jp = 0; jp < 8; jp += 2) {
                uint32_t off = (uint32_t)(b_el + jp * 8 * LDB + k0) * 2;
                uint32_t rh[4], rl[4];
                ldsm4(rh, bbh + off);
                ldsm4(rl, bbl + off);
                bh[jp][0] = rh[0]; bh[jp][1] = rh[1];
                bh[jp + 1][0] = rh[2]; bh[jp + 1][1] = rh[3];
                bl[jp][0] = rl[0]; bl[jp][1] = rl[1];
                bl[jp + 1][0] = rl[2]; bl[jp + 1][1] = rl[3];
            }
#pragma unroll
            for (int i = 0; i < 2; ++i)
#pragma unroll
                for (int j = 0; j < 8; ++j) {
                    mma_bf16(acc[i][j], ah[i], bh[j]);
                    mma_bf16(acc[i][j], ah[i], bl[j]);
                    mma_bf16(acc[i][j], al[i], bh[j]);
                }
        }

        // in-register scan: acc[i][j] = {(g,2t),(g,2t+1),(g+8,2t),(g+8,2t+1)}
        // slot s = 2*i + rh -> row = wm*32 + i*16 + rh*8 + g4
        const int kt_off = kt * 128 + wn * 64 + 2 * t4;
#pragma unroll
        for (int j = 0; j < 8; ++j) {
            int cb = kt_off + j * 8;
            float c2a = c2s[cb], c2b = c2s[cb + 1];
#pragma unroll
            for (int i = 0; i < 2; ++i) {
                float s0 = fmaf(-2.f, acc[i][j][0], c2a);
                float s1 = fmaf(-2.f, acc[i][j][1], c2b);
                float s2 = fmaf(-2.f, acc[i][j][2], c2a);
                float s3 = fmaf(-2.f, acc[i][j][3], c2b);
                int lo = 2 * i, hi = 2 * i + 1;
                if (s0 < bv[lo])       { bv2[lo] = bv[lo]; bv[lo] = s0; bik[lo] = cb; }
                else if (s0 < bv2[lo]) { bv2[lo] = s0; }
                if (s1 < bv[lo])       { bv2[lo] = bv[lo]; bv[lo] = s1; bik[lo] = cb + 1; }
                else if (s1 < bv2[lo]) { bv2[lo] = s1; }
                if (s2 < bv[hi])       { bv2[hi] = bv[hi]; bv[hi] = s2; bik[hi] = cb; }
                else if (s2 < bv2[hi]) { bv2[hi] = s2; }
                if (s3 < bv[hi])       { bv2[hi] = bv[hi]; bv[hi] = s3; bik[hi] = cb + 1; }
                else if (s3 < bv2[hi]) { bv2[hi] = s3; }
            }
        }
    }

    // quad merge (lanes of a quad hold the same rows, different cols)
#pragma unroll
    for (int s = 0; s < 4; ++s) {
#pragma unroll
        for (int off = 1; off <= 2; off <<= 1) {
            float ov1 = __shfl_xor_sync(0xffffffffu, bv[s],  off);
            float ov2 = __shfl_xor_sync(0xffffffffu, bv2[s], off);
            int   oi1 = __shfl_xor_sync(0xffffffffu, bik[s], off);
            comb2(bv[s], bik[s], bv2[s], ov1, oi1, ov2);
        }
    }

    // cross-wn merge via smem
    float* mg1 = (float*)(smem + SM_MG);          // [2][128]
    float* mg2 = mg1 + 256;
    int*   mgi = (int*)(mg2 + 256);
    __syncthreads();                    // everyone past last cp.async use of buffers
    if (t4 == 0) {
#pragma unroll
        for (int s = 0; s < 4; ++s) {
            int row = wm * 32 + (s >> 1) * 16 + (s & 1) * 8 + g4;
            mg1[wn * 128 + row] = bv[s];
            mg2[wn * 128 + row] = bv2[s];
            mgi[wn * 128 + row] = bik[s];
        }
    }
    __syncthreads();
    if (tid < 128) {
        float v1 = mg1[tid], v2 = mg2[tid];
        int   i1 = mgi[tid];
        comb2(v1, i1, v2, mg1[128 + tid], mgi[128 + tid], mg2[128 + tid]);
        int gn = nbase + tid;
        g_idx[gn] = i1;
        if (v2 - v1 < MARGIN_THRESH) {
            int pos = atomicAdd(&g_nflag, 1);
            g_flag[pos] = gn;
        }
    }
}

// ---------------- near-tie refine: bit-emulate the reference's fp32 arithmetic --------
__global__ __launch_bounds__(128) void refine_kernel(const float* __restrict__ x)
{
    __shared__ float xsh[DD];
    __shared__ float x2sh;
    __shared__ float bvs[128];
    __shared__ int   bis[128];
    const int tid = threadIdx.x;
    const int nflag = g_nflag;

    for (int f = blockIdx.x; f < nflag; f += gridDim.x) {
        int node = g_flag[f];
        xsh[tid] = x[(size_t)node * DD + tid];
        __syncthreads();
        if (tid == 0) {                  // sequential emulated x2 (overlaps dot loops)
            float acc = 0.f;
            for (int d = 0; d < DD; ++d)
                acc = __fadd_rn(acc, __fmul_rn(xsh[d], xsh[d]));
            x2sh = acc;
        }

        float dot[4];
#pragma unroll
        for (int j = 0; j < 4; ++j) {
            int k = j * 128 + tid;
            float dd = 0.f;
            for (int d = 0; d < DD; ++d)
                dd = __fmaf_rn(xsh[d], g_cbT[d * KK + k], dd);
            dot[j] = dd;
        }
        __syncthreads();
        float x2 = x2sh;

        float bestv = 3.4e38f; int besti = 0x7fffffff;
#pragma unroll
        for (int j = 0; j < 4; ++j) {
            int k = j * 128 + tid;
            float s = __fsub_rn(__fadd_rn(x2, g_c2e[k]), __fmul_rn(2.f, dot[j]));
            if (s < bestv || (s == bestv && k < besti)) { bestv = s; besti = k; }
        }
        bvs[tid] = bestv; bis[tid] = besti;
        __syncthreads();
        for (int st = 64; st > 0; st >>= 1) {
            if (tid < st) {
                float v2 = bvs[tid + st]; int k2 = bis[tid + st];
                if (v2 < bvs[tid] || (v2 == bvs[tid] && k2 < bis[tid])) {
                    bvs[tid] = v2; bis[tid] = k2;
                }
            }
            __syncthreads();
        }
        if (tid == 0) g_idx[node] = bis[0];
        __syncthreads();
    }
}

// ---------------- z_nodes gather: out_z[i] = codebook[idx[i]] ----------------
__global__ void gather_kernel(const float* __restrict__ cb, float* __restrict__ outz) {
    int gid = blockIdx.x * 256 + threadIdx.x;   // over N*32 float4s
    int i = gid >> 5, q = gid & 31;
    int k = g_idx[i];
    ((float4*)outz)[(size_t)i * 32 + q] = ((const float4*)cb)[(size_t)k * 32 + q];
}

// ---------------- per-graph pooling + tiny matmuls (128 threads, 4-warp split) -------
__global__ __launch_bounds__(128) void pool_kernel(
    const float* __restrict__ x, const float* __restrict__ causal,
    const float* __restrict__ counter, const float* __restrict__ fcw,
    const float* __restrict__ fcb, float* __restrict__ out)
{
    __shared__ float part[4][3][DD];   // per-warp partial sums
    __shared__ float pv[3][DD];
    __shared__ float wsh[TT * DD];
    const int g = blockIdx.x, tid = threadIdx.x;
    const int w = tid >> 5, t = tid & 31;

    for (int j = tid; j < TT * DD; j += 128) wsh[j] = fcw[j];

    const float4* x4 = (const float4*)x;
    const float4* a4 = (const float4*)causal;
    const float4* c4 = (const float4*)counter;

    int s = g_seg[g], e = g_seg[g + 1];
    float4 sx = {0,0,0,0}, sa = {0,0,0,0}, sc = {0,0,0,0};
#pragma unroll 2
    for (int i = s + w; i < e; i += 4) {
        int k = g_idx[i];
        float4 vx = x4[(size_t)i * 32 + t];
        float4 va = a4[(size_t)k * 32 + t];
        float4 vc = c4[(size_t)k * 32 + t];
        sx.x += vx.x; sx.y += vx.y; sx.z += vx.z; sx.w += vx.w;
        sa.x += va.x; sa.y += va.y; sa.z += va.z; sa.w += va.w;
        sc.x += vc.x; sc.y += vc.y; sc.z += vc.z; sc.w += vc.w;
    }
    ((float4*)part[w][0])[t] = sx;
    ((float4*)part[w][1])[t] = sa;
    ((float4*)part[w][2])[t] = sc;
    __syncthreads();

    float fx = (part[0][0][tid] + part[1][0][tid]) + (part[2][0][tid] + part[3][0][tid]);
    float fa = (part[0][1][tid] + part[1][1][tid]) + (part[2][1][tid] + part[3][1][tid]);
    float fc = (part[0][2][tid] + part[1][2][tid]) + (part[2][2][tid] + part[3][2][tid]);

    float cnt = (float)(e - s);
    float inv = 1.f / fmaxf(cnt, 1.f);
    float px  = fx * inv;
    float pca = (fx + fa) * inv;
    float pco = fc * inv;

    out[OFF_PCA + (size_t)g * DD + tid] = pca;
    out[OFF_PX  + (size_t)g * DD + tid] = px;

    pv[0][tid] = pca; pv[1][tid] = pco; pv[2][tid] = px;
    __syncthreads();

    if (tid < 3 * TT) {
        int v = tid / TT, tk = tid % TT;
        float acc = fcb[tk];
#pragma unroll 8
        for (int q = 0; q < DD; ++q) acc = fmaf(pv[v][q], wsh[tk * DD + q], acc);
        out[(size_t)v * (GG * TT) + g * TT + tk] = acc;
    }
}

extern "C" void kernel_launch(void* const* d_in, const int* in_sizes, int n_in,
                              void* d_out, int out_size) {
    const float* x        = (const float*)d_in[0];
    const int*   batch    = (const int*)  d_in[1];
    const float* codebook = (const float*)d_in[2];
    const float* causal   = (const float*)d_in[3];
    const float* counter  = (const float*)d_in[4];
    const float* fcw      = (const float*)d_in[5];
    const float* fcb      = (const float*)d_in[6];
    float* out = (float*)d_out;

    cudaFuncSetAttribute(argmin_tc,
                         cudaFuncAttributeMaxDynamicSharedMemorySize, SMEM_TC);

    setup_kernel<<<85, 256>>>(batch, causal);
    argmin_tc<<<NN / 128, 256, SMEM_TC>>>(x);
    refine_kernel<<<256, 128>>>(x);
    gather_kernel<<<(NN * 32) / 256, 256>>>(codebook, out + OFF_Z);
    pool_kernel<<<GG, 128>>>(x, causal, counter, fcw, fcb, out);
}

// round 14
// speedup vs baseline: 1.1577x; 1.1577x over previous
#include <cuda_runtime.h>
#include <cuda_bf16.h>
#include <mma.h>
#include <cstdint>

using namespace nvcuda;

#define NN 262144
#define DD 128
#define KK 512
#define GG 4096
#define TT 10

// output layout (float32, concatenated reference tuple)
#define OFF_CPRE   0
#define OFF_XPRE   (GG * TT)            // counter_pre
#define OFF_YPRE   (2 * GG * TT)
#define OFF_Z      (3 * GG * TT)
#define OFF_PCA    (OFF_Z + (size_t)NN * DD)
#define OFF_PX     (OFF_PCA + (size_t)GG * DD)

#define MARGIN_THRESH 0.01f

#define LDB 136                         // bf16 tile leading dim (elements)
#define LDP 132                         // fp32 score tile leading dim (elements)

#define BTILE_U4 4352                   // one code tile (bh+bl) in uint4s

// smem byte offsets (128-node CTA): [xh|xl][B0][B1][c2][merge]
#define SM_XH   0
#define SM_XL   34816
#define SM_B0   69632
#define SM_B1   139264
#define SM_C2   208896
#define SM_MG   210944                  // merge scratch + final idx
#define SMEM_TC 215040

__device__ int   g_idx[NN];
__device__ int   g_seg[GG + 1];
__device__ float g_c2[KK];       // fast-path c2
__device__ float g_c2e[KK];      // reference-emulated c2 (sequential fp32, no fma)
__device__ float g_cbT[DD * KK]; // transposed causal codebook for coalesced refine
__device__ int   g_flag[NN];
__device__ int   g_nflag;
__device__ uint4 g_cbs[4][BTILE_U4];   // pre-split codebook tiles: [bh | bl] blocked layout

// ---------------- cp.async helpers ----------------
__device__ __forceinline__ void cpa16(uint32_t saddr, const void* gptr) {
    asm volatile("cp.async.cg.shared.global [%0], [%1], 16;" :: "r"(saddr), "l"(gptr));
}
__device__ __forceinline__ void cpa_commit() { asm volatile("cp.async.commit_group;"); }
__device__ __forceinline__ void cpa_wait0() { asm volatile("cp.async.wait_group 0;"); }
__device__ __forceinline__ void cpa_wait1() { asm volatile("cp.async.wait_group 1;"); }

// symmetric top-2 merge with first-index tie-break
__device__ __forceinline__ void comb2(float& v1, int& i1, float& v2,
                                      float ov1, int oi1, float ov2) {
    if (ov1 < v1 || (ov1 == v1 && oi1 < i1)) {
        v2 = fminf(v1, ov2);
        v1 = ov1; i1 = oi1;
    } else {
        v2 = fminf(v2, ov1);
    }
}

// split one 8-float chunk to packed bf16 hi/lo uint4s
__device__ __forceinline__ void split8(const float* f, uint4& H, uint4& L) {
    uint32_t hp[4], lp[4];
#pragma unroll
    for (int j = 0; j < 4; ++j) {
        __nv_bfloat16 h0 = __float2bfloat16(f[2 * j]);
        __nv_bfloat16 h1 = __float2bfloat16(f[2 * j + 1]);
        __nv_bfloat16 l0 = __float2bfloat16(f[2 * j]     - __bfloat162float(h0));
        __nv_bfloat16 l1 = __float2bfloat16(f[2 * j + 1] - __bfloat162float(h1));
        hp[j] = ((uint32_t)__bfloat16_as_ushort(h1) << 16) | __bfloat16_as_ushort(h0);
        lp[j] = ((uint32_t)__bfloat16_as_ushort(l1) << 16) | __bfloat16_as_ushort(l0);
    }
    H = make_uint4(hp[0], hp[1], hp[2], hp[3]);
    L = make_uint4(lp[0], lp[1], lp[2], lp[3]);
}

// ---------------- fused setup: seg (blocks 0-16) + prep (17-80) + split (81-84) ------
__global__ __launch_bounds__(256) void setup_kernel(
    const int* __restrict__ bw, const float* __restrict__ cc)
{
    const int b = blockIdx.x;
    const int tid = threadIdx.x;
    if (b < 17) {
        int g = b * 256 + tid;
        if (g == 0) g_nflag = 0;
        if (g > GG) return;
        const int n = NN;
        bool is64 = (bw[n - 1] == 0) && (bw[n - 3] == 0);
        int lo = 0, hi = n;
        while (lo < hi) {
            int mid = (lo + hi) >> 1;
            int v = is64 ? bw[2 * mid] : bw[mid];
            if (v < g) lo = mid + 1; else hi = mid;
        }
        g_seg[g] = lo;
    } else if (b < 81) {
        int k = (b - 17) * 8 + (tid >> 5);
        int lane = tid & 31;
        float v[4];
        float s = 0.f;
#pragma unroll
        for (int j = 0; j < 4; ++j) {
            v[j] = cc[k * DD + lane + 32 * j];
            s = fmaf(v[j], v[j], s);
            g_cbT[(lane + 32 * j) * KK + k] = v[j];
        }
#pragma unroll
        for (int o = 16; o; o >>= 1) s += __shfl_xor_sync(0xffffffffu, s, o);
        if (lane == 0) g_c2[k] = s;
        if (lane == 0) {
            const float* r = cc + (size_t)k * DD;
            float acc = 0.f;
            for (int d = 0; d < DD; ++d)
                acc = __fadd_rn(acc, __fmul_rn(r[d], r[d]));
            g_c2e[k] = acc;
        }
    } else {
        const int kt = b - 81;
#pragma unroll
        for (int it = 0; it < 8; ++it) {
            int idx = it * 256 + tid;
            int row = idx >> 4, ch = idx & 15;
            float f[8];
            const float4* p = (const float4*)(cc + (size_t)(kt * 128 + row) * DD) + ch * 2;
            float4 v0 = p[0], v1 = p[1];
            f[0]=v0.x; f[1]=v0.y; f[2]=v0.z; f[3]=v0.w;
            f[4]=v1.x; f[5]=v1.y; f[6]=v1.z; f[7]=v1.w;
            uint4 H, L;
            split8(f, H, L);
            int u4 = row * 17 + ch;
            g_cbs[kt][u4] = H;
            g_cbs[kt][2176 + u4] = L;
        }
    }
}

// ---------------- HMMA argmin (round-11 mainloop) + fused z gather -------------------
__global__ __launch_bounds__(256) void argmin_tc(
    const float* __restrict__ x, const float* __restrict__ codebook,
    float* __restrict__ outz)
{
    extern __shared__ char smem[];
    __nv_bfloat16* xh  = (__nv_bfloat16*)(smem + SM_XH);
    __nv_bfloat16* xl  = (__nv_bfloat16*)(smem + SM_XL);
    float*         c2s = (float*)(smem + SM_C2);

    const int tid  = threadIdx.x;
    const int wid  = tid >> 5;
    const int lane = tid & 31;
    const int wm   = wid & 3;            // node block: rows 32*wm..
    const int wn   = wid >> 2;           // code block: cols 64*wn..
    const int nbase = blockIdx.x * 128;

    const uint32_t sb0 = (uint32_t)__cvta_generic_to_shared(smem + SM_B0);
    const uint32_t sb1 = (uint32_t)__cvta_generic_to_shared(smem + SM_B1);

    // prefetch tiles 0 and 1 (two groups in flight) while converting X
#pragma unroll
    for (int b = 0; b < 2; ++b) {
        const uint4* src = g_cbs[b];
        uint32_t dst = b ? sb1 : sb0;
#pragma unroll
        for (int i = 0; i < 17; ++i) {
            int idx = tid + 256 * i;
            cpa16(dst + idx * 16, src + idx);
        }
        cpa_commit();
    }

    // fill X (128 rows) bf16 hi/lo
#pragma unroll
    for (int it = 0; it < 8; ++it) {
        int idx = it * 256 + tid;        // 0..2047
        int row = idx >> 4, ch = idx & 15;
        const float4* p = (const float4*)(x + (size_t)(nbase + row) * DD) + ch * 2;
        float4 v0 = p[0], v1 = p[1];
        float f[8] = {v0.x, v0.y, v0.z, v0.w, v1.x, v1.y, v1.z, v1.w};
        uint4 H, L;
        split8(f, H, L);
        int eo = row * LDB + ch * 8;
        *(uint4*)((char*)xh + 2 * eo) = H;
        *(uint4*)((char*)xl + 2 * eo) = L;
    }
    for (int k = tid; k < KK; k += 256) c2s[k] = g_c2[k];

    float bestv = 3.4e38f, bestv2 = 3.4e38f;
    int   besti = 0x7fffffff;

    for (int kt = 0; kt < 4; ++kt) {
        if (kt > 0) {
            __syncthreads();             // scans of kt-1 (ps in buf((kt-1)&1)) complete
            if (kt <= 2) {               // prefetch tile kt+1 into buf((kt+1)&1)
                const uint4* src = g_cbs[kt + 1];
                uint32_t dst = ((kt + 1) & 1) ? sb1 : sb0;
#pragma unroll
                for (int i = 0; i < 17; ++i) {
                    int idx = tid + 256 * i;
                    cpa16(dst + idx * 16, src + idx);
                }
                cpa_commit();
            }
        }
        if (kt < 3) cpa_wait1(); else cpa_wait0();
        __syncthreads();                 // B(kt) visible to all (X too on kt=0)

        char* bbase = smem + ((kt & 1) ? SM_B1 : SM_B0);
        __nv_bfloat16* bh = (__nv_bfloat16*)bbase;
        __nv_bfloat16* bl = (__nv_bfloat16*)(bbase + 34816);
        float*         ps = (float*)bbase;

        wmma::fragment<wmma::accumulator, 16, 16, 16, float> acc[2][4];
#pragma unroll
        for (int i = 0; i < 2; ++i)
#pragma unroll
            for (int j = 0; j < 4; ++j) wmma::fill_fragment(acc[i][j], 0.f);

#pragma unroll
        for (int kk = 0; kk < 8; ++kk) {
            const int k0 = kk * 16;
            wmma::fragment<wmma::matrix_a, 16, 16, 16, __nv_bfloat16, wmma::row_major> ah[2], al[2];
            wmma::fragment<wmma::matrix_b, 16, 16, 16, __nv_bfloat16, wmma::col_major> bhf[4], blf[4];
#pragma unroll
            for (int i = 0; i < 2; ++i) {
                wmma::load_matrix_sync(ah[i], xh + (wm * 32 + i * 16) * LDB + k0, LDB);
                wmma::load_matrix_sync(al[i], xl + (wm * 32 + i * 16) * LDB + k0, LDB);
            }
#pragma unroll
            for (int j = 0; j < 4; ++j) {
                wmma::load_matrix_sync(bhf[j], bh + (wn * 64 + j * 16) * LDB + k0, LDB);
                wmma::load_matrix_sync(blf[j], bl + (wn * 64 + j * 16) * LDB + k0, LDB);
            }
#pragma unroll
            for (int i = 0; i < 2; ++i)
#pragma unroll
                for (int j = 0; j < 4; ++j) {
                    wmma::mma_sync(acc[i][j], ah[i], bhf[j], acc[i][j]);
                    wmma::mma_sync(acc[i][j], ah[i], blf[j], acc[i][j]);
                    wmma::mma_sync(acc[i][j], al[i], bhf[j], acc[i][j]);
                }
        }
        __syncthreads();                 // all warps done reading bh/bl

        // warp-local store into this warp's disjoint ps region
#pragma unroll
        for (int i = 0; i < 2; ++i)
#pragma unroll
            for (int j = 0; j < 4; ++j)
                wmma::store_matrix_sync(
                    ps + (wm * 32 + i * 16) * LDP + wn * 64 + j * 16,
                    acc[i][j], LDP, wmma::mem_row_major);
        __syncwarp();                    // warp-local visibility (no block barrier)

        // warp-local scan: thread=row (node wm*32+lane), 64 cols of this warp's half
        {
            const float4* row = (const float4*)(ps + (wm * 32 + lane) * LDP) + wn * 16;
#pragma unroll
            for (int q = 0; q < 16; ++q) {
                float4 v = row[q];
                float d4[4] = {v.x, v.y, v.z, v.w};
#pragma unroll
                for (int u = 0; u < 4; ++u) {
                    int k = kt * 128 + wn * 64 + 4 * q + u;
                    float s = fmaf(-2.f, d4[u], c2s[k]);
                    if (s < bestv)       { bestv2 = bestv; bestv = s; besti = k; }
                    else if (s < bestv2) { bestv2 = s; }
                }
            }
        }
    }

    // final cross-half merge: X region is dead after last mma
    __syncthreads();
    float* mv1 = (float*)(smem + SM_XH);            // [8][32]
    float* mv2 = mv1 + 256;                          // [8][32]
    int*   mi1 = (int*)(mv2 + 256);                  // [8][32]
    int*   fin = (int*)(smem + SM_MG);               // final idx [128]
    mv1[wid * 32 + lane] = bestv;
    mv2[wid * 32 + lane] = bestv2;
    mi1[wid * 32 + lane] = besti;
    __syncthreads();

    if (tid < 128) {
        int bm = tid >> 5, t = tid & 31;
        float v1 = mv1[bm * 32 + t], v2 = mv2[bm * 32 + t];
        int   i1 = mi1[bm * 32 + t];
        comb2(v1, i1, v2,
              mv1[(bm + 4) * 32 + t], mi1[(bm + 4) * 32 + t], mv2[(bm + 4) * 32 + t]);
        int gn = nbase + bm * 32 + t;
        g_idx[gn] = i1;
        fin[bm * 32 + t] = i1;
        if (v2 - v1 < MARGIN_THRESH) {
            int pos = atomicAdd(&g_nflag, 1);
            g_flag[pos] = gn;
        }
    }
    __syncthreads();

    // fused z gather: out_z[node] = codebook[idx[node]] (codebook rows hot in L2)
    const float4* cb4 = (const float4*)codebook;
    float4* oz4 = (float4*)outz;
#pragma unroll
    for (int it = 0; it < 16; ++it) {
        int idx = it * 256 + tid;        // over 128 nodes x 32 float4s
        int i = idx >> 5, q = idx & 31;
        int k = fin[i];
        oz4[(size_t)(nbase + i) * 32 + q] = cb4[(size_t)k * 32 + q];
    }
}

// ---------------- near-tie refine: bit-emulate reference fp32; patch idx + z ---------
__global__ __launch_bounds__(128) void refine_kernel(
    const float* __restrict__ x, const float* __restrict__ codebook,
    float* __restrict__ outz)
{
    __shared__ float xsh[DD];
    __shared__ float x2sh;
    __shared__ float bvs[128];
    __shared__ int   bis[128];
    const int tid = threadIdx.x;
    const int nflag = g_nflag;

    for (int f = blockIdx.x; f < nflag; f += gridDim.x) {
        int node = g_flag[f];
        xsh[tid] = x[(size_t)node * DD + tid];
        __syncthreads();
        if (tid == 0) {                  // sequential emulated x2, overlaps dot loops
            float acc = 0.f;
            for (int d = 0; d < DD; ++d)
                acc = __fadd_rn(acc, __fmul_rn(xsh[d], xsh[d]));
            x2sh = acc;
        }

        float dot[4];
#pragma unroll
        for (int j = 0; j < 4; ++j) {
            int k = j * 128 + tid;       // lane-consecutive k: coalesced
            float dd = 0.f;
            for (int d = 0; d < DD; ++d)
                dd = __fmaf_rn(xsh[d], g_cbT[d * KK + k], dd);
            dot[j] = dd;
        }
        __syncthreads();
        float x2 = x2sh;

        float bestv = 3.4e38f; int besti = 0x7fffffff;
#pragma unroll
        for (int j = 0; j < 4; ++j) {
            int k = j * 128 + tid;
            float s = __fsub_rn(__fadd_rn(x2, g_c2e[k]), __fmul_rn(2.f, dot[j]));
            if (s < bestv || (s == bestv && k < besti)) { bestv = s; besti = k; }
        }
        bvs[tid] = bestv; bis[tid] = besti;
        __syncthreads();
        for (int st = 64; st > 0; st >>= 1) {
            if (tid < st) {
                float v2 = bvs[tid + st]; int k2 = bis[tid + st];
                if (v2 < bvs[tid] || (v2 == bvs[tid] && k2 < bis[tid])) {
                    bvs[tid] = v2; bis[tid] = k2;
                }
            }
            __syncthreads();
        }
        int kw = bis[0];
        if (tid == 0) g_idx[node] = kw;
        // patch z row (cheap; only flagged nodes)
        outz[(size_t)node * DD + tid] = codebook[(size_t)kw * DD + tid];
        __syncthreads();
    }
}

// ---------------- per-graph pooling + tiny matmuls (128 threads, 4-warp split) -------
__global__ __launch_bounds__(128) void pool_kernel(
    const float* __restrict__ x, const float* __restrict__ causal,
    const float* __restrict__ counter, const float* __restrict__ fcw,
    const float* __restrict__ fcb, float* __restrict__ out)
{
    __shared__ float part[4][3][DD];   // per-warp partial sums
    __shared__ float pv[3][DD];
    __shared__ float wsh[TT * DD];
    const int g = blockIdx.x, tid = threadIdx.x;
    const int w = tid >> 5, t = tid & 31;

    for (int j = tid; j < TT * DD; j += 128) wsh[j] = fcw[j];

    const float4* x4 = (const float4*)x;
    const float4* a4 = (const float4*)causal;
    const float4* c4 = (const float4*)counter;

    int s = g_seg[g], e = g_seg[g + 1];
    float4 sx = {0,0,0,0}, sa = {0,0,0,0}, sc = {0,0,0,0};
#pragma unroll 2
    for (int i = s + w; i < e; i += 4) {
        int k = g_idx[i];
        float4 vx = x4[(size_t)i * 32 + t];
        float4 va = a4[(size_t)k * 32 + t];
        float4 vc = c4[(size_t)k * 32 + t];
        sx.x += vx.x; sx.y += vx.y; sx.z += vx.z; sx.w += vx.w;
        sa.x += va.x; sa.y += va.y; sa.z += va.z; sa.w += va.w;
        sc.x += vc.x; sc.y += vc.y; sc.z += vc.z; sc.w += vc.w;
    }
    ((float4*)part[w][0])[t] = sx;
    ((float4*)part[w][1])[t] = sa;
    ((float4*)part[w][2])[t] = sc;
    __syncthreads();

    float fx = (part[0][0][tid] + part[1][0][tid]) + (part[2][0][tid] + part[3][0][tid]);
    float fa = (part[0][1][tid] + part[1][1][tid]) + (part[2][1][tid] + part[3][1][tid]);
    float fc = (part[0][2][tid] + part[1][2][tid]) + (part[2][2][tid] + part[3][2][tid]);

    float cnt = (float)(e - s);
    float inv = 1.f / fmaxf(cnt, 1.f);
    float px  = fx * inv;
    float pca = (fx + fa) * inv;
    float pco = fc * inv;

    out[OFF_PCA + (size_t)g * DD + tid] = pca;
    out[OFF_PX  + (size_t)g * DD + tid] = px;

    pv[0][tid] = pca; pv[1][tid] = pco; pv[2][tid] = px;
    __syncthreads();

    if (tid < 3 * TT) {
        int v = tid / TT, tk = tid % TT;
        float acc = fcb[tk];
#pragma unroll 8
        for (int q = 0; q < DD; ++q) acc = fmaf(pv[v][q], wsh[tk * DD + q], acc);
        out[(size_t)v * (GG * TT) + g * TT + tk] = acc;
    }
}

extern "C" void kernel_launch(void* const* d_in, const int* in_sizes, int n_in,
                              void* d_out, int out_size) {
    const float* x        = (const float*)d_in[0];
    const int*   batch    = (const int*)  d_in[1];
    const float* codebook = (const float*)d_in[2];
    const float* causal   = (const float*)d_in[3];
    const float* counter  = (const float*)d_in[4];
    const float* fcw      = (const float*)d_in[5];
    const float* fcb      = (const float*)d_in[6];
    float* out = (float*)d_out;

    cudaFuncSetAttribute(argmin_tc,
                         cudaFuncAttributeMaxDynamicSharedMemorySize, SMEM_TC);

    setup_kernel<<<85, 256>>>(batch, causal);
    argmin_tc<<<NN / 128, 256, SMEM_TC>>>(x, codebook, out + OFF_Z);
    refine_kernel<<<256, 128>>>(x, codebook, out + OFF_Z);
    pool_kernel<<<GG, 128>>>(x, causal, counter, fcw, fcb, out);
}

// round 15
// speedup vs baseline: 1.6631x; 1.4366x over previous
#include <cuda_runtime.h>
#include <cuda_fp16.h>
#include <mma.h>
#include <cstdint>

using namespace nvcuda;

#define NN 262144
#define DD 128
#define KK 512
#define GG 4096
#define TT 10

// output layout (float32, concatenated reference tuple)
#define OFF_CPRE   0
#define OFF_XPRE   (GG * TT)            // counter_pre
#define OFF_YPRE   (2 * GG * TT)
#define OFF_Z      (3 * GG * TT)
#define OFF_PCA    (OFF_Z + (size_t)NN * DD)
#define OFF_PX     (OFF_PCA + (size_t)GG * DD)

#define MARGIN_THRESH 0.06f

#define LDB 136                         // fp16 tile leading dim (elements)
#define LDP 132                         // fp32 score tile leading dim (elements)

#define BTILE_U4 2176                   // one fp16 code tile in uint4s (128*136*2/16)

// smem byte offsets (128-node CTA): [xh][B0][B1][ps][c2][fin]
#define SM_XH   0
#define SM_B0   34816
#define SM_B1   69632
#define SM_PS   104448                  // 128*132*4 = 67584
#define SM_C2   172032                  // 2048
#define SM_MG   174080                  // final idx [128] + pad
#define SMEM_TC 178176

__device__ int   g_idx[NN];
__device__ int   g_seg[GG + 1];
__device__ float g_c2[KK];       // fast-path c2
__device__ float g_c2e[KK];      // reference-emulated c2 (sequential fp32, no fma)
__device__ float g_cbT[DD * KK]; // transposed causal codebook for coalesced refine
__device__ int   g_flag[NN];
__device__ int   g_nflag;
__device__ uint4 g_cbs[4][BTILE_U4];   // pre-converted fp16 codebook tiles

// ---------------- cp.async helpers ----------------
__device__ __forceinline__ void cpa16(uint32_t saddr, const void* gptr) {
    asm volatile("cp.async.cg.shared.global [%0], [%1], 16;" :: "r"(saddr), "l"(gptr));
}
__device__ __forceinline__ void cpa_commit() { asm volatile("cp.async.commit_group;"); }
__device__ __forceinline__ void cpa_wait0() { asm volatile("cp.async.wait_group 0;"); }
__device__ __forceinline__ void cpa_wait1() { asm volatile("cp.async.wait_group 1;"); }

// symmetric top-2 merge with first-index tie-break
__device__ __forceinline__ void comb2(float& v1, int& i1, float& v2,
                                      float ov1, int oi1, float ov2) {
    if (ov1 < v1 || (ov1 == v1 && oi1 < i1)) {
        v2 = fminf(v1, ov2);
        v1 = ov1; i1 = oi1;
    } else {
        v2 = fminf(v2, ov1);
    }
}

// convert one 8-float chunk to packed fp16 uint4
__device__ __forceinline__ uint4 pack8h(const float* f) {
    uint32_t hp[4];
#pragma unroll
    for (int j = 0; j < 4; ++j) {
        __half h0 = __float2half_rn(f[2 * j]);
        __half h1 = __float2half_rn(f[2 * j + 1]);
        hp[j] = ((uint32_t)__half_as_ushort(h1) << 16) | __half_as_ushort(h0);
    }
    return make_uint4(hp[0], hp[1], hp[2], hp[3]);
}

// ---------------- fused setup: seg (blocks 0-16) + prep (17-80) + split (81-84) ------
__global__ __launch_bounds__(256) void setup_kernel(
    const int* __restrict__ bw, const float* __restrict__ cc)
{
    const int b = blockIdx.x;
    const int tid = threadIdx.x;
    if (b < 17) {
        int g = b * 256 + tid;
        if (g == 0) g_nflag = 0;
        if (g > GG) return;
        const int n = NN;
        bool is64 = (bw[n - 1] == 0) && (bw[n - 3] == 0);
        int lo = 0, hi = n;
        while (lo < hi) {
            int mid = (lo + hi) >> 1;
            int v = is64 ? bw[2 * mid] : bw[mid];
            if (v < g) lo = mid + 1; else hi = mid;
        }
        g_seg[g] = lo;
    } else if (b < 81) {
        int k = (b - 17) * 8 + (tid >> 5);
        int lane = tid & 31;
        float v[4];
        float s = 0.f;
#pragma unroll
        for (int j = 0; j < 4; ++j) {
            v[j] = cc[k * DD + lane + 32 * j];
            s = fmaf(v[j], v[j], s);
            g_cbT[(lane + 32 * j) * KK + k] = v[j];
        }
#pragma unroll
        for (int o = 16; o; o >>= 1) s += __shfl_xor_sync(0xffffffffu, s, o);
        if (lane == 0) g_c2[k] = s;
        if (lane == 0) {
            const float* r = cc + (size_t)k * DD;
            float acc = 0.f;
            for (int d = 0; d < DD; ++d)
                acc = __fadd_rn(acc, __fmul_rn(r[d], r[d]));
            g_c2e[k] = acc;
        }
    } else {
        const int kt = b - 81;
#pragma unroll
        for (int it = 0; it < 8; ++it) {
            int idx = it * 256 + tid;    // 0..2047
            int row = idx >> 4, ch = idx & 15;
            float f[8];
            const float4* p = (const float4*)(cc + (size_t)(kt * 128 + row) * DD) + ch * 2;
            float4 v0 = p[0], v1 = p[1];
            f[0]=v0.x; f[1]=v0.y; f[2]=v0.z; f[3]=v0.w;
            f[4]=v1.x; f[5]=v1.y; f[6]=v1.z; f[7]=v1.w;
            g_cbs[kt][row * 17 + ch] = pack8h(f);
        }
    }
}

// ---------------- HMMA argmin: fp16 single-pass + fused z gather ---------------------
__global__ __launch_bounds__(256) void argmin_tc(
    const float* __restrict__ x, const float* __restrict__ codebook,
    float* __restrict__ outz)
{
    extern __shared__ char smem[];
    __half* xh  = (__half*)(smem + SM_XH);
    float*  ps  = (float*)(smem + SM_PS);
    float*  c2s = (float*)(smem + SM_C2);

    const int tid  = threadIdx.x;
    const int wid  = tid >> 5;
    const int lane = tid & 31;
    const int wm   = wid & 3;            // node block: rows 32*wm..
    const int wn   = wid >> 2;           // code block: cols 64*wn..
    const int nbase = blockIdx.x * 128;

    const uint32_t sb0 = (uint32_t)__cvta_generic_to_shared(smem + SM_B0);
    const uint32_t sb1 = (uint32_t)__cvta_generic_to_shared(smem + SM_B1);

    // prefetch tiles 0 and 1 (two groups in flight) while converting X
#pragma unroll
    for (int b = 0; b < 2; ++b) {
        const uint4* src = g_cbs[b];
        uint32_t dst = b ? sb1 : sb0;
#pragma unroll
        for (int i = 0; i < 9; ++i) {
            int idx = tid + 256 * i;
            if (idx < BTILE_U4) cpa16(dst + idx * 16, src + idx);
        }
        cpa_commit();
    }

    // fill X (128 rows) fp16
#pragma unroll
    for (int it = 0; it < 8; ++it) {
        int idx = it * 256 + tid;        // 0..2047
        int row = idx >> 4, ch = idx & 15;
        const float4* p = (const float4*)(x + (size_t)(nbase + row) * DD) + ch * 2;
        float4 v0 = p[0], v1 = p[1];
        float f[8] = {v0.x, v0.y, v0.z, v0.w, v1.x, v1.y, v1.z, v1.w};
        *(uint4*)((char*)xh + 2 * (row * LDB + ch * 8)) = pack8h(f);
    }
    for (int k = tid; k < KK; k += 256) c2s[k] = g_c2[k];

    float bestv = 3.4e38f, bestv2 = 3.4e38f;
    int   besti = 0x7fffffff;

    for (int kt = 0; kt < 4; ++kt) {
        if (kt > 0) {
            __syncthreads();             // all warps done LDSM of B(kt-1) + scan(kt-1)
            if (kt <= 2) {               // prefetch tile kt+1 into buf((kt+1)&1)
                const uint4* src = g_cbs[kt + 1];
                uint32_t dst = ((kt + 1) & 1) ? sb1 : sb0;
#pragma unroll
                for (int i = 0; i < 9; ++i) {
                    int idx = tid + 256 * i;
                    if (idx < BTILE_U4) cpa16(dst + idx * 16, src + idx);
                }
                cpa_commit();
            }
        }
        if (kt < 3) cpa_wait1(); else cpa_wait0();
        __syncthreads();                 // B(kt) visible to all (X too on kt=0)

        __half* bh = (__half*)(smem + ((kt & 1) ? SM_B1 : SM_B0));

        wmma::fragment<wmma::accumulator, 16, 16, 16, float> acc[2][4];
#pragma unroll
        for (int i = 0; i < 2; ++i)
#pragma unroll
            for (int j = 0; j < 4; ++j) wmma::fill_fragment(acc[i][j], 0.f);

#pragma unroll
        for (int kk = 0; kk < 8; ++kk) {
            const int k0 = kk * 16;
            wmma::fragment<wmma::matrix_a, 16, 16, 16, __half, wmma::row_major> ah[2];
            wmma::fragment<wmma::matrix_b, 16, 16, 16, __half, wmma::col_major> bhf[4];
#pragma unroll
            for (int i = 0; i < 2; ++i)
                wmma::load_matrix_sync(ah[i], xh + (wm * 32 + i * 16) * LDB + k0, LDB);
#pragma unroll
            for (int j = 0; j < 4; ++j)
                wmma::load_matrix_sync(bhf[j], bh + (wn * 64 + j * 16) * LDB + k0, LDB);
#pragma unroll
            for (int i = 0; i < 2; ++i)
#pragma unroll
                for (int j = 0; j < 4; ++j)
                    wmma::mma_sync(acc[i][j], ah[i], bhf[j], acc[i][j]);
        }

        // store into this warp's disjoint (dedicated) ps region
#pragma unroll
        for (int i = 0; i < 2; ++i)
#pragma unroll
            for (int j = 0; j < 4; ++j)
                wmma::store_matrix_sync(
                    ps + (wm * 32 + i * 16) * LDP + wn * 64 + j * 16,
                    acc[i][j], LDP, wmma::mem_row_major);
        __syncwarp();                    // warp-local visibility

        // warp-local scan with min4 fast path (k ascending: first-min preserved)
        {
            const float4* row = (const float4*)(ps + (wm * 32 + lane) * LDP) + wn * 16;
#pragma unroll
            for (int q = 0; q < 16; ++q) {
                float4 v = row[q];
                int kb = kt * 128 + wn * 64 + 4 * q;
                float s0 = fmaf(-2.f, v.x, c2s[kb]);
                float s1 = fmaf(-2.f, v.y, c2s[kb + 1]);
                float s2 = fmaf(-2.f, v.z, c2s[kb + 2]);
                float s3 = fmaf(-2.f, v.w, c2s[kb + 3]);
                float m = fminf(fminf(s0, s1), fminf(s2, s3));
                if (m < bestv2) {        // rare path: exact sequential top-2 update
                    float sv[4] = {s0, s1, s2, s3};
#pragma unroll
                    for (int u = 0; u < 4; ++u) {
                        float s = sv[u];
                        if (s < bestv)       { bestv2 = bestv; bestv = s; besti = kb + u; }
                        else if (s < bestv2) { bestv2 = s; }
                    }
                }
            }
        }
    }

    // final cross-half merge: X region is dead after last mma
    __syncthreads();
    float* mv1 = (float*)(smem + SM_XH);            // [8][32]
    float* mv2 = mv1 + 256;                          // [8][32]
    int*   mi1 = (int*)(mv2 + 256);                  // [8][32]
    int*   fin = (int*)(smem + SM_MG);               // final idx [128]
    mv1[wid * 32 + lane] = bestv;
    mv2[wid * 32 + lane] = bestv2;
    mi1[wid * 32 + lane] = besti;
    __syncthreads();

    if (tid < 128) {
        int bm = tid >> 5, t = tid & 31;
        float v1 = mv1[bm * 32 + t], v2 = mv2[bm * 32 + t];
        int   i1 = mi1[bm * 32 + t];
        comb2(v1, i1, v2,
              mv1[(bm + 4) * 32 + t], mi1[(bm + 4) * 32 + t], mv2[(bm + 4) * 32 + t]);
        int gn = nbase + bm * 32 + t;
        g_idx[gn] = i1;
        fin[bm * 32 + t] = i1;
        if (v2 - v1 < MARGIN_THRESH) {
            int pos = atomicAdd(&g_nflag, 1);
            g_flag[pos] = gn;
        }
    }
    __syncthreads();

    // fused z gather: out_z[node] = codebook[idx[node]] (codebook rows hot in L2)
    const float4* cb4 = (const float4*)codebook;
    float4* oz4 = (float4*)outz;
#pragma unroll
    for (int it = 0; it < 16; ++it) {
        int idx = it * 256 + tid;        // over 128 nodes x 32 float4s
        int i = idx >> 5, q = idx & 31;
        int k = fin[i];
        oz4[(size_t)(nbase + i) * 32 + q] = cb4[(size_t)k * 32 + q];
    }
}

// ---------------- batched near-tie refine: 16 nodes/block, reference-bit-exact -------
__global__ __launch_bounds__(256) void refine_kernel(
    const float* __restrict__ x, const float* __restrict__ codebook,
    float* __restrict__ outz)
{
    __shared__ float xsh[16][DD];
    __shared__ float x2sh[16];
    __shared__ float wv[8];
    __shared__ int   wi[8];
    __shared__ int   kwsh[16];
    const int tid = threadIdx.x;
    const int lane = tid & 31;
    const int wrp  = tid >> 5;
    const int nflag = g_nflag;
    const int nchunk = (nflag + 15) / 16;

    for (int c = blockIdx.x; c < nchunk; c += gridDim.x) {
        int base = c * 16;
        int cnt = min(16, nflag - base);

        for (int i = tid; i < cnt * DD; i += 256) {
            int n = i >> 7, d = i & 127;
            xsh[n][d] = x[(size_t)g_flag[base + n] * DD + d];
        }
        __syncthreads();
        if (tid < cnt) {                 // sequential emulated x2 per node
            float acc = 0.f;
            for (int d = 0; d < DD; ++d)
                acc = __fadd_rn(acc, __fmul_rn(xsh[tid][d], xsh[tid][d]));
            x2sh[tid] = acc;
        }
        __syncthreads();

        // dots for codes k = tid and tid+256, all nodes, d-outer (cbT streamed once)
        float acc[16][2];
#pragma unroll
        for (int n = 0; n < 16; ++n) { acc[n][0] = 0.f; acc[n][1] = 0.f; }
        for (int d = 0; d < DD; ++d) {
            float c0 = g_cbT[d * KK + tid];
            float c1 = g_cbT[d * KK + tid + 256];
#pragma unroll
            for (int n = 0; n < 16; ++n) {
                float xv = xsh[n][d];
                acc[n][0] = __fmaf_rn(xv, c0, acc[n][0]);
                acc[n][1] = __fmaf_rn(xv, c1, acc[n][1]);
            }
        }

        float c2e0 = g_c2e[tid], c2e1 = g_c2e[tid + 256];

        // per-node reduction over 512 codes (first-index tie-break)
        for (int n = 0; n < cnt; ++n) {
            float x2 = x2sh[n];
            float s0 = __fsub_rn(__fadd_rn(x2, c2e0), __fmul_rn(2.f, acc[n][0]));
            float s1 = __fsub_rn(__fadd_rn(x2, c2e1), __fmul_rn(2.f, acc[n][1]));
            float bv; int bk;
            if (s0 <= s1) { bv = s0; bk = tid; } else { bv = s1; bk = tid + 256; }
#pragma unroll
            for (int o = 16; o; o >>= 1) {
                float ov = __shfl_xor_sync(0xffffffffu, bv, o);
                int   ok = __shfl_xor_sync(0xffffffffu, bk, o);
                if (ov < bv || (ov == bv && ok < bk)) { bv = ov; bk = ok; }
            }
            if (lane == 0) { wv[wrp] = bv; wi[wrp] = bk; }
            __syncthreads();
            if (tid == 0) {
                float fv = wv[0]; int fk = wi[0];
#pragma unroll
                for (int w = 1; w < 8; ++w) {
                    if (wv[w] < fv || (wv[w] == fv && wi[w] < fk)) { fv = wv[w]; fk = wi[w]; }
                }
                kwsh[n] = fk;
                g_idx[g_flag[base + n]] = fk;
            }
            __syncthreads();
        }

        // patch z rows
        for (int i = tid; i < cnt * DD; i += 256) {
            int n = i >> 7, d = i & 127;
            outz[(size_t)g_flag[base + n] * DD + d] = codebook[(size_t)kwsh[n] * DD + d];
        }
        __syncthreads();
    }
}

// ---------------- per-graph pooling + tiny matmuls (128 threads, 4-warp split) -------
__global__ __launch_bounds__(128) void pool_kernel(
    const float* __restrict__ x, const float* __restrict__ causal,
    const float* __restrict__ counter, const float* __restrict__ fcw,
    const float* __restrict__ fcb, float* __restrict__ out)
{
    __shared__ float part[4][3][DD];   // per-warp partial sums
    __shared__ float pv[3][DD];
    __shared__ float wsh[TT * DD];
    const int g = blockIdx.x, tid = threadIdx.x;
    const int w = tid >> 5, t = tid & 31;

    for (int j = tid; j < TT * DD; j += 128) wsh[j] = fcw[j];

    const float4* x4 = (const float4*)x;
    const float4* a4 = (const float4*)causal;
    const float4* c4 = (const float4*)counter;

    int s = g_seg[g], e = g_seg[g + 1];
    float4 sx = {0,0,0,0}, sa = {0,0,0,0}, sc = {0,0,0,0};
#pragma unroll 2
    for (int i = s + w; i < e; i += 4) {
        int k = g_idx[i];
        float4 vx = x4[(size_t)i * 32 + t];
        float4 va = a4[(size_t)k * 32 + t];
        float4 vc = c4[(size_t)k * 32 + t];
        sx.x += vx.x; sx.y += vx.y; sx.z += vx.z; sx.w += vx.w;
        sa.x += va.x; sa.y += va.y; sa.z += va.z; sa.w += va.w;
        sc.x += vc.x; sc.y += vc.y; sc.z += vc.z; sc.w += vc.w;
    }
    ((float4*)part[w][0])[t] = sx;
    ((float4*)part[w][1])[t] = sa;
    ((float4*)part[w][2])[t] = sc;
    __syncthreads();

    float fx = (part[0][0][tid] + part[1][0][tid]) + (part[2][0][tid] + part[3][0][tid]);
    float fa = (part[0][1][tid] + part[1][1][tid]) + (part[2][1][tid] + part[3][1][tid]);
    float fc = (part[0][2][tid] + part[1][2][tid]) + (part[2][2][tid] + part[3][2][tid]);

    float cnt = (float)(e - s);
    float inv = 1.f / fmaxf(cnt, 1.f);
    float px  = fx * inv;
    float pca = (fx + fa) * inv;
    float pco = fc * inv;

    out[OFF_PCA + (size_t)g * DD + tid] = pca;
    out[OFF_PX  + (size_t)g * DD + tid] = px;

    pv[0][tid] = pca; pv[1][tid] = pco; pv[2][tid] = px;
    __syncthreads();

    if (tid < 3 * TT) {
        int v = tid / TT, tk = tid % TT;
        float acc = fcb[tk];
#pragma unroll 8
        for (int q = 0; q < DD; ++q) acc = fmaf(pv[v][q], wsh[tk * DD + q], acc);
        out[(size_t)v * (GG * TT) + g * TT + tk] = acc;
    }
}

extern "C" void kernel_launch(void* const* d_in, const int* in_sizes, int n_in,
                              void* d_out, int out_size) {
    const float* x        = (const float*)d_in[0];
    const int*   batch    = (const int*)  d_in[1];
    const float* codebook = (const float*)d_in[2];
    const float* causal   = (const float*)d_in[3];
    const float* counter  = (const float*)d_in[4];
    const float* fcw      = (const float*)d_in[5];
    const float* fcb      = (const float*)d_in[6];
    float* out = (float*)d_out;

    cudaFuncSetAttribute(argmin_tc,
                         cudaFuncAttributeMaxDynamicSharedMemorySize, SMEM_TC);

    setup_kernel<<<85, 256>>>(batch, causal);
    argmin_tc<<<NN / 128, 256, SMEM_TC>>>(x, codebook, out + OFF_Z);
    refine_kernel<<<592, 256>>>(x, codebook, out + OFF_Z);
    pool_kernel<<<GG, 128>>>(x, causal, counter, fcw, fcb, out);
}

// round 16
// speedup vs baseline: 1.6741x; 1.0066x over previous
#include <cuda_runtime.h>
#include <cuda_fp16.h>
#include <mma.h>
#include <cstdint>

using namespace nvcuda;

#define NN 262144
#define DD 128
#define KK 512
#define GG 4096
#define TT 10

// output layout (float32, concatenated reference tuple)
#define OFF_CPRE   0
#define OFF_XPRE   (GG * TT)            // counter_pre
#define OFF_YPRE   (2 * GG * TT)
#define OFF_Z      (3 * GG * TT)
#define OFF_PCA    (OFF_Z + (size_t)NN * DD)
#define OFF_PX     (OFF_PCA + (size_t)GG * DD)

#define MARGIN_THRESH 0.06f

#define LDB 136                         // fp16 tile leading dim (elements)
#define LDP 132                         // fp32 score tile leading dim (elements)

#define BTILE_U4 2176                   // one fp16 code tile in uint4s (128*136*2/16)

// smem byte offsets (128-node CTA): [xh][B0][B1][ps][c2][fin]
#define SM_XH   0
#define SM_B0   34816
#define SM_B1   69632
#define SM_PS   104448                  // 128*132*4 = 67584
#define SM_C2   172032                  // 2048
#define SM_MG   174080                  // final idx [128] + pad
#define SMEM_TC 178176

__device__ int   g_idx[NN];
__device__ int   g_seg[GG + 1];
__device__ float g_c2[KK];       // fast-path c2
__device__ float g_c2e[KK];      // reference-emulated c2 (sequential fp32, no fma)
__device__ float g_cbT[DD * KK]; // transposed causal codebook for coalesced refine
__device__ int   g_flag[NN];
__device__ int   g_nflag;
__device__ uint4 g_cbs[4][BTILE_U4];   // pre-converted fp16 codebook tiles

// ---------------- cp.async helpers ----------------
__device__ __forceinline__ void cpa16(uint32_t saddr, const void* gptr) {
    asm volatile("cp.async.cg.shared.global [%0], [%1], 16;" :: "r"(saddr), "l"(gptr));
}
__device__ __forceinline__ void cpa_commit() { asm volatile("cp.async.commit_group;"); }
__device__ __forceinline__ void cpa_wait0() { asm volatile("cp.async.wait_group 0;"); }
__device__ __forceinline__ void cpa_wait1() { asm volatile("cp.async.wait_group 1;"); }

// symmetric top-2 merge with first-index tie-break
__device__ __forceinline__ void comb2(float& v1, int& i1, float& v2,
                                      float ov1, int oi1, float ov2) {
    if (ov1 < v1 || (ov1 == v1 && oi1 < i1)) {
        v2 = fminf(v1, ov2);
        v1 = ov1; i1 = oi1;
    } else {
        v2 = fminf(v2, ov1);
    }
}

// convert one 8-float chunk to packed fp16 uint4
__device__ __forceinline__ uint4 pack8h(const float* f) {
    uint32_t hp[4];
#pragma unroll
    for (int j = 0; j < 4; ++j) {
        __half h0 = __float2half_rn(f[2 * j]);
        __half h1 = __float2half_rn(f[2 * j + 1]);
        hp[j] = ((uint32_t)__half_as_ushort(h1) << 16) | __half_as_ushort(h0);
    }
    return make_uint4(hp[0], hp[1], hp[2], hp[3]);
}

// ---------------- fused setup: seg (blocks 0-16) + prep (17-80) + split (81-84) ------
__global__ __launch_bounds__(256) void setup_kernel(
    const int* __restrict__ bw, const float* __restrict__ cc)
{
    const int b = blockIdx.x;
    const int tid = threadIdx.x;
    if (b < 17) {
        int g = b * 256 + tid;
        if (g == 0) g_nflag = 0;
        if (g > GG) return;
        const int n = NN;
        bool is64 = (bw[n - 1] == 0) && (bw[n - 3] == 0);
        int lo = 0, hi = n;
        while (lo < hi) {
            int mid = (lo + hi) >> 1;
            int v = is64 ? bw[2 * mid] : bw[mid];
            if (v < g) lo = mid + 1; else hi = mid;
        }
        g_seg[g] = lo;
    } else if (b < 81) {
        int k = (b - 17) * 8 + (tid >> 5);
        int lane = tid & 31;
        float v[4];
        float s = 0.f;
#pragma unroll
        for (int j = 0; j < 4; ++j) {
            v[j] = cc[k * DD + lane + 32 * j];
            s = fmaf(v[j], v[j], s);
            g_cbT[(lane + 32 * j) * KK + k] = v[j];
        }
#pragma unroll
        for (int o = 16; o; o >>= 1) s += __shfl_xor_sync(0xffffffffu, s, o);
        if (lane == 0) g_c2[k] = s;
        if (lane == 0) {
            const float* r = cc + (size_t)k * DD;
            float acc = 0.f;
            for (int d = 0; d < DD; ++d)
                acc = __fadd_rn(acc, __fmul_rn(r[d], r[d]));
            g_c2e[k] = acc;
        }
    } else {
        const int kt = b - 81;
#pragma unroll
        for (int it = 0; it < 8; ++it) {
            int idx = it * 256 + tid;    // 0..2047
            int row = idx >> 4, ch = idx & 15;
            float f[8];
            const float4* p = (const float4*)(cc + (size_t)(kt * 128 + row) * DD) + ch * 2;
            float4 v0 = p[0], v1 = p[1];
            f[0]=v0.x; f[1]=v0.y; f[2]=v0.z; f[3]=v0.w;
            f[4]=v1.x; f[5]=v1.y; f[6]=v1.z; f[7]=v1.w;
            g_cbs[kt][row * 17 + ch] = pack8h(f);
        }
    }
}

// ---------------- HMMA argmin: fp16 single-pass + fused z gather ---------------------
__global__ __launch_bounds__(256) void argmin_tc(
    const float* __restrict__ x, const float* __restrict__ codebook,
    float* __restrict__ outz)
{
    extern __shared__ char smem[];
    __half* xh  = (__half*)(smem + SM_XH);
    float*  ps  = (float*)(smem + SM_PS);
    float*  c2s = (float*)(smem + SM_C2);

    const int tid  = threadIdx.x;
    const int wid  = tid >> 5;
    const int lane = tid & 31;
    const int wm   = wid & 3;            // node block: rows 32*wm..
    const int wn   = wid >> 2;           // code block: cols 64*wn..
    const int nbase = blockIdx.x * 128;

    const uint32_t sb0 = (uint32_t)__cvta_generic_to_shared(smem + SM_B0);
    const uint32_t sb1 = (uint32_t)__cvta_generic_to_shared(smem + SM_B1);

    // prefetch tiles 0 and 1 (two groups in flight) while converting X
#pragma unroll
    for (int b = 0; b < 2; ++b) {
        const uint4* src = g_cbs[b];
        uint32_t dst = b ? sb1 : sb0;
#pragma unroll
        for (int i = 0; i < 9; ++i) {
            int idx = tid + 256 * i;
            if (idx < BTILE_U4) cpa16(dst + idx * 16, src + idx);
        }
        cpa_commit();
    }

    // fill X (128 rows) fp16
#pragma unroll
    for (int it = 0; it < 8; ++it) {
        int idx = it * 256 + tid;        // 0..2047
        int row = idx >> 4, ch = idx & 15;
        const float4* p = (const float4*)(x + (size_t)(nbase + row) * DD) + ch * 2;
        float4 v0 = p[0], v1 = p[1];
        float f[8] = {v0.x, v0.y, v0.z, v0.w, v1.x, v1.y, v1.z, v1.w};
        *(uint4*)((char*)xh + 2 * (row * LDB + ch * 8)) = pack8h(f);
    }
    for (int k = tid; k < KK; k += 256) c2s[k] = g_c2[k];

    float bestv = 3.4e38f, bestv2 = 3.4e38f;
    int   besti = 0x7fffffff;

    for (int kt = 0; kt < 4; ++kt) {
        if (kt > 0) {
            __syncthreads();             // all warps done LDSM of B(kt-1) + scan(kt-1)
            if (kt <= 2) {               // prefetch tile kt+1 into buf((kt+1)&1)
                const uint4* src = g_cbs[kt + 1];
                uint32_t dst = ((kt + 1) & 1) ? sb1 : sb0;
#pragma unroll
                for (int i = 0; i < 9; ++i) {
                    int idx = tid + 256 * i;
                    if (idx < BTILE_U4) cpa16(dst + idx * 16, src + idx);
                }
                cpa_commit();
            }
        }
        if (kt < 3) cpa_wait1(); else cpa_wait0();
        __syncthreads();                 // B(kt) visible to all (X too on kt=0)

        __half* bh = (__half*)(smem + ((kt & 1) ? SM_B1 : SM_B0));

        wmma::fragment<wmma::accumulator, 16, 16, 16, float> acc[2][4];
#pragma unroll
        for (int i = 0; i < 2; ++i)
#pragma unroll
            for (int j = 0; j < 4; ++j) wmma::fill_fragment(acc[i][j], 0.f);

#pragma unroll
        for (int kk = 0; kk < 8; ++kk) {
            const int k0 = kk * 16;
            wmma::fragment<wmma::matrix_a, 16, 16, 16, __half, wmma::row_major> ah[2];
            wmma::fragment<wmma::matrix_b, 16, 16, 16, __half, wmma::col_major> bhf[4];
#pragma unroll
            for (int i = 0; i < 2; ++i)
                wmma::load_matrix_sync(ah[i], xh + (wm * 32 + i * 16) * LDB + k0, LDB);
#pragma unroll
            for (int j = 0; j < 4; ++j)
                wmma::load_matrix_sync(bhf[j], bh + (wn * 64 + j * 16) * LDB + k0, LDB);
#pragma unroll
            for (int i = 0; i < 2; ++i)
#pragma unroll
                for (int j = 0; j < 4; ++j)
                    wmma::mma_sync(acc[i][j], ah[i], bhf[j], acc[i][j]);
        }

        // store into this warp's disjoint (dedicated) ps region
#pragma unroll
        for (int i = 0; i < 2; ++i)
#pragma unroll
            for (int j = 0; j < 4; ++j)
                wmma::store_matrix_sync(
                    ps + (wm * 32 + i * 16) * LDP + wn * 64 + j * 16,
                    acc[i][j], LDP, wmma::mem_row_major);
        __syncwarp();                    // warp-local visibility

        // warp-local scan with min4 fast path (k ascending: first-min preserved)
        {
            const float4* row = (const float4*)(ps + (wm * 32 + lane) * LDP) + wn * 16;
#pragma unroll
            for (int q = 0; q < 16; ++q) {
                float4 v = row[q];
                int kb = kt * 128 + wn * 64 + 4 * q;
                float s0 = fmaf(-2.f, v.x, c2s[kb]);
                float s1 = fmaf(-2.f, v.y, c2s[kb + 1]);
                float s2 = fmaf(-2.f, v.z, c2s[kb + 2]);
                float s3 = fmaf(-2.f, v.w, c2s[kb + 3]);
                float m = fminf(fminf(s0, s1), fminf(s2, s3));
                if (m < bestv2) {        // rare path: exact sequential top-2 update
                    float sv[4] = {s0, s1, s2, s3};
#pragma unroll
                    for (int u = 0; u < 4; ++u) {
                        float s = sv[u];
                        if (s < bestv)       { bestv2 = bestv; bestv = s; besti = kb + u; }
                        else if (s < bestv2) { bestv2 = s; }
                    }
                }
            }
        }
    }

    // final cross-half merge: X region is dead after last mma
    __syncthreads();
    float* mv1 = (float*)(smem + SM_XH);            // [8][32]
    float* mv2 = mv1 + 256;                          // [8][32]
    int*   mi1 = (int*)(mv2 + 256);                  // [8][32]
    int*   fin = (int*)(smem + SM_MG);               // final idx [128]
    mv1[wid * 32 + lane] = bestv;
    mv2[wid * 32 + lane] = bestv2;
    mi1[wid * 32 + lane] = besti;
    __syncthreads();

    if (tid < 128) {
        int bm = tid >> 5, t = tid & 31;
        float v1 = mv1[bm * 32 + t], v2 = mv2[bm * 32 + t];
        int   i1 = mi1[bm * 32 + t];
        comb2(v1, i1, v2,
              mv1[(bm + 4) * 32 + t], mi1[(bm + 4) * 32 + t], mv2[(bm + 4) * 32 + t]);
        int gn = nbase + bm * 32 + t;
        g_idx[gn] = i1;
        fin[bm * 32 + t] = i1;
        if (v2 - v1 < MARGIN_THRESH) {
            int pos = atomicAdd(&g_nflag, 1);
            g_flag[pos] = gn;
        }
    }
    __syncthreads();

    // fused z gather: out_z[node] = codebook[idx[node]] (codebook rows hot in L2)
    const float4* cb4 = (const float4*)codebook;
    float4* oz4 = (float4*)outz;
#pragma unroll
    for (int it = 0; it < 16; ++it) {
        int idx = it * 256 + tid;        // over 128 nodes x 32 float4s
        int i = idx >> 5, q = idx & 31;
        int k = fin[i];
        oz4[(size_t)(nbase + i) * 32 + q] = cb4[(size_t)k * 32 + q];
    }
}

// ---------------- batched near-tie refine: 16 nodes/block, reference-bit-exact -------
__global__ __launch_bounds__(256) void refine_kernel(
    const float* __restrict__ x, const float* __restrict__ codebook,
    float* __restrict__ outz)
{
    __shared__ float xsh[16][DD];
    __shared__ float x2sh[16];
    __shared__ float wv[8];
    __shared__ int   wi[8];
    __shared__ int   kwsh[16];
    const int tid = threadIdx.x;
    const int lane = tid & 31;
    const int wrp  = tid >> 5;
    const int nflag = g_nflag;
    const int nchunk = (nflag + 15) / 16;

    for (int c = blockIdx.x; c < nchunk; c += gridDim.x) {
        int base = c * 16;
        int cnt = min(16, nflag - base);

        for (int i = tid; i < cnt * DD; i += 256) {
            int n = i >> 7, d = i & 127;
            xsh[n][d] = x[(size_t)g_flag[base + n] * DD + d];
        }
        __syncthreads();
        if (tid < cnt) {                 // sequential emulated x2 per node
            float acc = 0.f;
            for (int d = 0; d < DD; ++d)
                acc = __fadd_rn(acc, __fmul_rn(xsh[tid][d], xsh[tid][d]));
            x2sh[tid] = acc;
        }
        __syncthreads();

        // dots for codes k = tid and tid+256, all nodes, d-outer (cbT streamed once)
        float acc[16][2];
#pragma unroll
        for (int n = 0; n < 16; ++n) { acc[n][0] = 0.f; acc[n][1] = 0.f; }
        for (int d = 0; d < DD; ++d) {
            float c0 = g_cbT[d * KK + tid];
            float c1 = g_cbT[d * KK + tid + 256];
#pragma unroll
            for (int n = 0; n < 16; ++n) {
                float xv = xsh[n][d];
                acc[n][0] = __fmaf_rn(xv, c0, acc[n][0]);
                acc[n][1] = __fmaf_rn(xv, c1, acc[n][1]);
            }
        }

        float c2e0 = g_c2e[tid], c2e1 = g_c2e[tid + 256];

        // per-node reduction over 512 codes (first-index tie-break)
        for (int n = 0; n < cnt; ++n) {
            float x2 = x2sh[n];
            float s0 = __fsub_rn(__fadd_rn(x2, c2e0), __fmul_rn(2.f, acc[n][0]));
            float s1 = __fsub_rn(__fadd_rn(x2, c2e1), __fmul_rn(2.f, acc[n][1]));
            float bv; int bk;
            if (s0 <= s1) { bv = s0; bk = tid; } else { bv = s1; bk = tid + 256; }
#pragma unroll
            for (int o = 16; o; o >>= 1) {
                float ov = __shfl_xor_sync(0xffffffffu, bv, o);
                int   ok = __shfl_xor_sync(0xffffffffu, bk, o);
                if (ov < bv || (ov == bv && ok < bk)) { bv = ov; bk = ok; }
            }
            if (lane == 0) { wv[wrp] = bv; wi[wrp] = bk; }
            __syncthreads();
            if (tid == 0) {
                float fv = wv[0]; int fk = wi[0];
#pragma unroll
                for (int w = 1; w < 8; ++w) {
                    if (wv[w] < fv || (wv[w] == fv && wi[w] < fk)) { fv = wv[w]; fk = wi[w]; }
                }
                kwsh[n] = fk;
                g_idx[g_flag[base + n]] = fk;
            }
            __syncthreads();
        }

        // patch z rows
        for (int i = tid; i < cnt * DD; i += 256) {
            int n = i >> 7, d = i & 127;
            outz[(size_t)g_flag[base + n] * DD + d] = codebook[(size_t)kwsh[n] * DD + d];
        }
        __syncthreads();
    }
}

// ---------------- per-graph pooling + tiny matmuls (256 threads, 8-warp split) -------
__global__ __launch_bounds__(256) void pool_kernel(
    const float* __restrict__ x, const float* __restrict__ causal,
    const float* __restrict__ counter, const float* __restrict__ fcw,
    const float* __restrict__ fcb, float* __restrict__ out)
{
    __shared__ float part[8][3][DD];   // per-warp partial sums
    __shared__ float pv[3][DD];
    __shared__ float wsh[TT * DD];
    const int g = blockIdx.x, tid = threadIdx.x;
    const int w = tid >> 5, t = tid & 31;

    for (int j = tid; j < TT * DD; j += 256) wsh[j] = fcw[j];

    const float4* x4 = (const float4*)x;
    const float4* a4 = (const float4*)causal;
    const float4* c4 = (const float4*)counter;

    int s = g_seg[g], e = g_seg[g + 1];
    float4 sx = {0,0,0,0}, sa = {0,0,0,0}, sc = {0,0,0,0};
#pragma unroll 2
    for (int i = s + w; i < e; i += 8) {
        int k = g_idx[i];
        float4 vx = x4[(size_t)i * 32 + t];
        float4 va = a4[(size_t)k * 32 + t];
        float4 vc = c4[(size_t)k * 32 + t];
        sx.x += vx.x; sx.y += vx.y; sx.z += vx.z; sx.w += vx.w;
        sa.x += va.x; sa.y += va.y; sa.z += va.z; sa.w += va.w;
        sc.x += vc.x; sc.y += vc.y; sc.z += vc.z; sc.w += vc.w;
    }
    ((float4*)part[w][0])[t] = sx;
    ((float4*)part[w][1])[t] = sa;
    ((float4*)part[w][2])[t] = sc;
    __syncthreads();

    if (tid < 128) {
        float fx = ((part[0][0][tid] + part[1][0][tid]) + (part[2][0][tid] + part[3][0][tid]))
                 + ((part[4][0][tid] + part[5][0][tid]) + (part[6][0][tid] + part[7][0][tid]));
        float fa = ((part[0][1][tid] + part[1][1][tid]) + (part[2][1][tid] + part[3][1][tid]))
                 + ((part[4][1][tid] + part[5][1][tid]) + (part[6][1][tid] + part[7][1][tid]));
        float fc = ((part[0][2][tid] + part[1][2][tid]) + (part[2][2][tid] + part[3][2][tid]))
                 + ((part[4][2][tid] + part[5][2][tid]) + (part[6][2][tid] + part[7][2][tid]));

        float cnt = (float)(e - s);
        float inv = 1.f / fmaxf(cnt, 1.f);
        float px  = fx * inv;
        float pca = (fx + fa) * inv;
        float pco = fc * inv;

        out[OFF_PCA + (size_t)g * DD + tid] = pca;
        out[OFF_PX  + (size_t)g * DD + tid] = px;

        pv[0][tid] = pca; pv[1][tid] = pco; pv[2][tid] = px;
    }
    __syncthreads();

    if (tid < 3 * TT) {
        int v = tid / TT, tk = tid % TT;
        float acc = fcb[tk];
#pragma unroll 8
        for (int q = 0; q < DD; ++q) acc = fmaf(pv[v][q], wsh[tk * DD + q], acc);
        out[(size_t)v * (GG * TT) + g * TT + tk] = acc;
    }
}

extern "C" void kernel_launch(void* const* d_in, const int* in_sizes, int n_in,
                              void* d_out, int out_size) {
    const float* x        = (const float*)d_in[0];
    const int*   batch    = (const int*)  d_in[1];
    const float* codebook = (const float*)d_in[2];
    const float* causal   = (const float*)d_in[3];
    const float* counter  = (const float*)d_in[4];
    const float* fcw      = (const float*)d_in[5];
    const float* fcb      = (const float*)d_in[6];
    float* out = (float*)d_out;

    cudaFuncSetAttribute(argmin_tc,
                         cudaFuncAttributeMaxDynamicSharedMemorySize, SMEM_TC);

    setup_kernel<<<85, 256>>>(batch, causal);
    argmin_tc<<<NN / 128, 256, SMEM_TC>>>(x, codebook, out + OFF_Z);
    refine_kernel<<<592, 256>>>(x, codebook, out + OFF_Z);
    pool_kernel<<<GG, 256>>>(x, causal, counter, fcw, fcb, out);
}

// round 17
// speedup vs baseline: 1.7104x; 1.0217x over previous
#include <cuda_runtime.h>
#include <cuda_fp16.h>
#include <mma.h>
#include <cstdint>

using namespace nvcuda;

#define NN 262144
#define DD 128
#define KK 512
#define GG 4096
#define TT 10

// output layout (float32, concatenated reference tuple)
#define OFF_CPRE   0
#define OFF_XPRE   (GG * TT)            // counter_pre
#define OFF_YPRE   (2 * GG * TT)
#define OFF_Z      (3 * GG * TT)
#define OFF_PCA    (OFF_Z + (size_t)NN * DD)
#define OFF_PX     (OFF_PCA + (size_t)GG * DD)

#define MARGIN_THRESH 0.06f

#define LDB 136                         // fp16 tile leading dim (elements)
#define LDS_STG 68                      // staging leading dim (floats)

#define BTILE_U4 2176                   // one fp16 code tile in uint4s (128*136*2/16)

// smem byte offsets (128-node CTA, 2 CTA/SM): [xh][B][stg][c2][mg][fin]
#define SM_XH   0
#define SM_B    34816
#define SM_ST   69632                   // 8 warps x 16x68 floats = 34816
#define SM_C2   104448                  // 2048
#define SM_MG   106496                  // mv1/mv2[256]f + mi1[256]i = 3072
#define SM_FIN  109568                  // fin[128] int
#define SMEM_TC 110080

__device__ int   g_idx[NN];
__device__ int   g_seg[GG + 1];
__device__ float g_c2[KK];       // fast-path c2
__device__ float g_c2e[KK];      // reference-emulated c2 (sequential fp32, no fma)
__device__ float g_cbT[DD * KK]; // transposed causal codebook for coalesced refine
__device__ int   g_flag[NN];
__device__ int   g_nflag;
__device__ uint4 g_cbs[4][BTILE_U4];   // pre-converted fp16 codebook tiles

// ---------------- cp.async helpers ----------------
__device__ __forceinline__ void cpa16(uint32_t saddr, const void* gptr) {
    asm volatile("cp.async.cg.shared.global [%0], [%1], 16;" :: "r"(saddr), "l"(gptr));
}
__device__ __forceinline__ void cpa_commit() { asm volatile("cp.async.commit_group;"); }
__device__ __forceinline__ void cpa_wait0() { asm volatile("cp.async.wait_group 0;"); }

// symmetric top-2 merge with first-index tie-break
__device__ __forceinline__ void comb2(float& v1, int& i1, float& v2,
                                      float ov1, int oi1, float ov2) {
    if (ov1 < v1 || (ov1 == v1 && oi1 < i1)) {
        v2 = fminf(v1, ov2);
        v1 = ov1; i1 = oi1;
    } else {
        v2 = fminf(v2, ov1);
    }
}

// convert one 8-float chunk to packed fp16 uint4
__device__ __forceinline__ uint4 pack8h(const float* f) {
    uint32_t hp[4];
#pragma unroll
    for (int j = 0; j < 4; ++j) {
        __half h0 = __float2half_rn(f[2 * j]);
        __half h1 = __float2half_rn(f[2 * j + 1]);
        hp[j] = ((uint32_t)__half_as_ushort(h1) << 16) | __half_as_ushort(h0);
    }
    return make_uint4(hp[0], hp[1], hp[2], hp[3]);
}

// ---------------- fused setup: seg (blocks 0-16) + prep (17-80) + split (81-84) ------
__global__ __launch_bounds__(256) void setup_kernel(
    const int* __restrict__ bw, const float* __restrict__ cc)
{
    const int b = blockIdx.x;
    const int tid = threadIdx.x;
    if (b < 17) {
        int g = b * 256 + tid;
        if (g == 0) g_nflag = 0;
        if (g > GG) return;
        const int n = NN;
        bool is64 = (bw[n - 1] == 0) && (bw[n - 3] == 0);
        int lo = 0, hi = n;
        while (lo < hi) {
            int mid = (lo + hi) >> 1;
            int v = is64 ? bw[2 * mid] : bw[mid];
            if (v < g) lo = mid + 1; else hi = mid;
        }
        g_seg[g] = lo;
    } else if (b < 81) {
        int k = (b - 17) * 8 + (tid >> 5);
        int lane = tid & 31;
        float v[4];
        float s = 0.f;
#pragma unroll
        for (int j = 0; j < 4; ++j) {
            v[j] = cc[k * DD + lane + 32 * j];
            s = fmaf(v[j], v[j], s);
            g_cbT[(lane + 32 * j) * KK + k] = v[j];
        }
#pragma unroll
        for (int o = 16; o; o >>= 1) s += __shfl_xor_sync(0xffffffffu, s, o);
        if (lane == 0) g_c2[k] = s;
        if (lane == 0) {
            const float* r = cc + (size_t)k * DD;
            float acc = 0.f;
            for (int d = 0; d < DD; ++d)
                acc = __fadd_rn(acc, __fmul_rn(r[d], r[d]));
            g_c2e[k] = acc;
        }
    } else {
        const int kt = b - 81;
#pragma unroll
        for (int it = 0; it < 8; ++it) {
            int idx = it * 256 + tid;    // 0..2047
            int row = idx >> 4, ch = idx & 15;
            float f[8];
            const float4* p = (const float4*)(cc + (size_t)(kt * 128 + row) * DD) + ch * 2;
            float4 v0 = p[0], v1 = p[1];
            f[0]=v0.x; f[1]=v0.y; f[2]=v0.z; f[3]=v0.w;
            f[4]=v1.x; f[5]=v1.y; f[6]=v1.z; f[7]=v1.w;
            g_cbs[kt][row * 17 + ch] = pack8h(f);
        }
    }
}

// ---------------- HMMA argmin: fp16 1-pass, 2 CTA/SM, staged scan, fused z gather ----
__global__ __launch_bounds__(256, 2) void argmin_tc(
    const float* __restrict__ x, const float* __restrict__ codebook,
    float* __restrict__ outz)
{
    extern __shared__ char smem[];
    __half* xh  = (__half*)(smem + SM_XH);
    __half* bsh = (__half*)(smem + SM_B);
    float*  c2s = (float*)(smem + SM_C2);

    const int tid  = threadIdx.x;
    const int wid  = tid >> 5;
    const int lane = tid & 31;
    const int wm   = wid & 3;            // node block: rows 32*wm..
    const int wn   = wid >> 2;           // code block: cols 64*wn..
    const int nbase = blockIdx.x * 128;

    const uint32_t sb = (uint32_t)__cvta_generic_to_shared(smem + SM_B);
    float* stg = (float*)(smem + SM_ST) + wid * (16 * LDS_STG);

    // prefetch B tile 0 while converting X
    {
        const uint4* src = g_cbs[0];
#pragma unroll
        for (int i = 0; i < 9; ++i) {
            int idx = tid + 256 * i;
            if (idx < BTILE_U4) cpa16(sb + idx * 16, src + idx);
        }
        cpa_commit();
    }

    // fill X (128 rows) fp16
#pragma unroll
    for (int it = 0; it < 8; ++it) {
        int idx = it * 256 + tid;        // 0..2047
        int row = idx >> 4, ch = idx & 15;
        const float4* p = (const float4*)(x + (size_t)(nbase + row) * DD) + ch * 2;
        float4 v0 = p[0], v1 = p[1];
        float f[8] = {v0.x, v0.y, v0.z, v0.w, v1.x, v1.y, v1.z, v1.w};
        *(uint4*)((char*)xh + 2 * (row * LDB + ch * 8)) = pack8h(f);
    }
    for (int k = tid; k < KK; k += 256) c2s[k] = g_c2[k];

    // per-thread top-2 state: slot s = i-half (rows wm*32 + s*16 + (lane&15)),
    // this thread covers cols wn*64 + (lane>>4)*32 .. +32 of each row.
    float bv[2]  = {3.4e38f, 3.4e38f};
    float bv2[2] = {3.4e38f, 3.4e38f};
    int   bik[2] = {0x7fffffff, 0x7fffffff};

    const int row16 = lane & 15;
    const int chalf = lane >> 4;

    for (int kt = 0; kt < 4; ++kt) {
        cpa_wait0();
        __syncthreads();                 // B(kt) ready; X/c2 ready on kt=0

        wmma::fragment<wmma::accumulator, 16, 16, 16, float> acc[2][4];
#pragma unroll
        for (int i = 0; i < 2; ++i)
#pragma unroll
            for (int j = 0; j < 4; ++j) wmma::fill_fragment(acc[i][j], 0.f);

#pragma unroll
        for (int kk = 0; kk < 8; ++kk) {
            const int k0 = kk * 16;
            wmma::fragment<wmma::matrix_a, 16, 16, 16, __half, wmma::row_major> ah[2];
            wmma::fragment<wmma::matrix_b, 16, 16, 16, __half, wmma::col_major> bhf[4];
#pragma unroll
            for (int i = 0; i < 2; ++i)
                wmma::load_matrix_sync(ah[i], xh + (wm * 32 + i * 16) * LDB + k0, LDB);
#pragma unroll
            for (int j = 0; j < 4; ++j)
                wmma::load_matrix_sync(bhf[j], bsh + (wn * 64 + j * 16) * LDB + k0, LDB);
#pragma unroll
            for (int i = 0; i < 2; ++i)
#pragma unroll
                for (int j = 0; j < 4; ++j)
                    wmma::mma_sync(acc[i][j], ah[i], bhf[j], acc[i][j]);
        }
        __syncthreads();                 // all warps done reading B(kt)

        if (kt < 3) {                    // copy of B(kt+1) overlaps the staged scan
            const uint4* src = g_cbs[kt + 1];
#pragma unroll
            for (int i = 0; i < 9; ++i) {
                int idx = tid + 256 * i;
                if (idx < BTILE_U4) cpa16(sb + idx * 16, src + idx);
            }
            cpa_commit();
        }

        // staged scan: two 16x64 halves through the warp-private buffer
#pragma unroll
        for (int i = 0; i < 2; ++i) {
#pragma unroll
            for (int j = 0; j < 4; ++j)
                wmma::store_matrix_sync(stg + j * 16, acc[i][j], LDS_STG,
                                        wmma::mem_row_major);
            __syncwarp();
            const float4* rp = (const float4*)(stg + row16 * LDS_STG) + chalf * 8;
#pragma unroll
            for (int q = 0; q < 8; ++q) {
                float4 v = rp[q];
                int kb = kt * 128 + wn * 64 + chalf * 32 + 4 * q;
                float s0 = fmaf(-2.f, v.x, c2s[kb]);
                float s1 = fmaf(-2.f, v.y, c2s[kb + 1]);
                float s2 = fmaf(-2.f, v.z, c2s[kb + 2]);
                float s3 = fmaf(-2.f, v.w, c2s[kb + 3]);
                float m = fminf(fminf(s0, s1), fminf(s2, s3));
                if (m < bv2[i]) {        // rare: exact sequential top-2 update
                    float sv[4] = {s0, s1, s2, s3};
#pragma unroll
                    for (int u = 0; u < 4; ++u) {
                        float s = sv[u];
                        if (s < bv[i])       { bv2[i] = bv[i]; bv[i] = s; bik[i] = kb + u; }
                        else if (s < bv2[i]) { bv2[i] = s; }
                    }
                }
            }
            __syncwarp();                // scan done before next half overwrites stg
        }
    }

    // merge col-halves (lane l <-> l+16 share the same rows)
#pragma unroll
    for (int s = 0; s < 2; ++s) {
        float ov1 = __shfl_xor_sync(0xffffffffu, bv[s],  16);
        float ov2 = __shfl_xor_sync(0xffffffffu, bv2[s], 16);
        int   oi1 = __shfl_xor_sync(0xffffffffu, bik[s], 16);
        comb2(bv[s], bik[s], bv2[s], ov1, oi1, ov2);
    }

    // cross-wn merge via smem
    float* mv1 = (float*)(smem + SM_MG);            // [2][128]
    float* mv2 = mv1 + 256;
    int*   mi1 = (int*)(mv2 + 256);
    int*   fin = (int*)(smem + SM_FIN);             // [128]
    __syncthreads();
    if (lane < 16) {
#pragma unroll
        for (int s = 0; s < 2; ++s) {
            int row = wm * 32 + s * 16 + lane;
            mv1[wn * 128 + row] = bv[s];
            mv2[wn * 128 + row] = bv2[s];
            mi1[wn * 128 + row] = bik[s];
        }
    }
    __syncthreads();

    if (tid < 128) {
        float v1 = mv1[tid], v2 = mv2[tid];
        int   i1 = mi1[tid];
        comb2(v1, i1, v2, mv1[128 + tid], mi1[128 + tid], mv2[128 + tid]);
        int gn = nbase + tid;
        g_idx[gn] = i1;
        fin[tid] = i1;
        if (v2 - v1 < MARGIN_THRESH) {
            int pos = atomicAdd(&g_nflag, 1);
            g_flag[pos] = gn;
        }
    }
    __syncthreads();

    // fused z gather: out_z[node] = codebook[idx[node]] (codebook rows hot in L2)
    const float4* cb4 = (const float4*)codebook;
    float4* oz4 = (float4*)outz;
#pragma unroll
    for (int it = 0; it < 16; ++it) {
        int idx = it * 256 + tid;        // over 128 nodes x 32 float4s
        int i = idx >> 5, q = idx & 31;
        int k = fin[i];
        oz4[(size_t)(nbase + i) * 32 + q] = cb4[(size_t)k * 32 + q];
    }
}

// ---------------- batched near-tie refine: 16 nodes/block, reference-bit-exact -------
__global__ __launch_bounds__(256) void refine_kernel(
    const float* __restrict__ x, const float* __restrict__ codebook,
    float* __restrict__ outz)
{
    __shared__ float xsh[16][DD];
    __shared__ float x2sh[16];
    __shared__ float wv[8];
    __shared__ int   wi[8];
    __shared__ int   kwsh[16];
    const int tid = threadIdx.x;
    const int lane = tid & 31;
    const int wrp  = tid >> 5;
    const int nflag = g_nflag;
    const int nchunk = (nflag + 15) / 16;

    for (int c = blockIdx.x; c < nchunk; c += gridDim.x) {
        int base = c * 16;
        int cnt = min(16, nflag - base);

        for (int i = tid; i < cnt * DD; i += 256) {
            int n = i >> 7, d = i & 127;
            xsh[n][d] = x[(size_t)g_flag[base + n] * DD + d];
        }
        __syncthreads();
        if (tid < cnt) {                 // sequential emulated x2 per node
            float acc = 0.f;
            for (int d = 0; d < DD; ++d)
                acc = __fadd_rn(acc, __fmul_rn(xsh[tid][d], xsh[tid][d]));
            x2sh[tid] = acc;
        }
        __syncthreads();

        // dots for codes k = tid and tid+256, all nodes, d-outer (cbT streamed once)
        float acc[16][2];
#pragma unroll
        for (int n = 0; n < 16; ++n) { acc[n][0] = 0.f; acc[n][1] = 0.f; }
        for (int d = 0; d < DD; ++d) {
            float c0 = g_cbT[d * KK + tid];
            float c1 = g_cbT[d * KK + tid + 256];
#pragma unroll
            for (int n = 0; n < 16; ++n) {
                float xv = xsh[n][d];
                acc[n][0] = __fmaf_rn(xv, c0, acc[n][0]);
                acc[n][1] = __fmaf_rn(xv, c1, acc[n][1]);
            }
        }

        float c2e0 = g_c2e[tid], c2e1 = g_c2e[tid + 256];

        // per-node reduction over 512 codes (first-index tie-break)
        for (int n = 0; n < cnt; ++n) {
            float x2 = x2sh[n];
            float s0 = __fsub_rn(__fadd_rn(x2, c2e0), __fmul_rn(2.f, acc[n][0]));
            float s1 = __fsub_rn(__fadd_rn(x2, c2e1), __fmul_rn(2.f, acc[n][1]));
            float bv; int bk;
            if (s0 <= s1) { bv = s0; bk = tid; } else { bv = s1; bk = tid + 256; }
#pragma unroll
            for (int o = 16; o; o >>= 1) {
                float ov = __shfl_xor_sync(0xffffffffu, bv, o);
                int   ok = __shfl_xor_sync(0xffffffffu, bk, o);
                if (ov < bv || (ov == bv && ok < bk)) { bv = ov; bk = ok; }
            }
            if (lane == 0) { wv[wrp] = bv; wi[wrp] = bk; }
            __syncthreads();
            if (tid == 0) {
                float fv = wv[0]; int fk = wi[0];
#pragma unroll
                for (int w = 1; w < 8; ++w) {
                    if (wv[w] < fv || (wv[w] == fv && wi[w] < fk)) { fv = wv[w]; fk = wi[w]; }
                }
                kwsh[n] = fk;
                g_idx[g_flag[base + n]] = fk;
            }
            __syncthreads();
        }

        // patch z rows
        for (int i = tid; i < cnt * DD; i += 256) {
            int n = i >> 7, d = i & 127;
            outz[(size_t)g_flag[base + n] * DD + d] = codebook[(size_t)kwsh[n] * DD + d];
        }
        __syncthreads();
    }
}

// ---------------- per-graph pooling + tiny matmuls (256 threads, 8-warp split) -------
__global__ __launch_bounds__(256) void pool_kernel(
    const float* __restrict__ x, const float* __restrict__ causal,
    const float* __restrict__ counter, const float* __restrict__ fcw,
    const float* __restrict__ fcb, float* __restrict__ out)
{
    __shared__ float part[8][3][DD];   // per-warp partial sums
    __shared__ float pv[3][DD];
    __shared__ float wsh[TT * DD];
    const int g = blockIdx.x, tid = threadIdx.x;
    const int w = tid >> 5, t = tid & 31;

    for (int j = tid; j < TT * DD; j += 256) wsh[j] = fcw[j];

    const float4* x4 = (const float4*)x;
    const float4* a4 = (const float4*)causal;
    const float4* c4 = (const float4*)counter;

    int s = g_seg[g], e = g_seg[g + 1];
    float4 sx = {0,0,0,0}, sa = {0,0,0,0}, sc = {0,0,0,0};
#pragma unroll 2
    for (int i = s + w; i < e; i += 8) {
        int k = g_idx[i];
        float4 vx = x4[(size_t)i * 32 + t];
        float4 va = a4[(size_t)k * 32 + t];
        float4 vc = c4[(size_t)k * 32 + t];
        sx.x += vx.x; sx.y += vx.y; sx.z += vx.z; sx.w += vx.w;
        sa.x += va.x; sa.y += va.y; sa.z += va.z; sa.w += va.w;
        sc.x += vc.x; sc.y += vc.y; sc.z += vc.z; sc.w += vc.w;
    }
    ((float4*)part[w][0])[t] = sx;
    ((float4*)part[w][1])[t] = sa;
    ((float4*)part[w][2])[t] = sc;
    __syncthreads();

    if (tid < 128) {
        float fx = ((part[0][0][tid] + part[1][0][tid]) + (part[2][0][tid] + part[3][0][tid]))
                 + ((part[4][0][tid] + part[5][0][tid]) + (part[6][0][tid] + part[7][0][tid]));
        float fa = ((part[0][1][tid] + part[1][1][tid]) + (part[2][1][tid] + part[3][1][tid]))
                 + ((part[4][1][tid] + part[5][1][tid]) + (part[6][1][tid] + part[7][1][tid]));
        float fc = ((part[0][2][tid] + part[1][2][tid]) + (part[2][2][tid] + part[3][2][tid]))
                 + ((part[4][2][tid] + part[5][2][tid]) + (part[6][2][tid] + part[7][2][tid]));

        float cnt = (float)(e - s);
        float inv = 1.f / fmaxf(cnt, 1.f);
        float px  = fx * inv;
        float pca = (fx + fa) * inv;
        float pco = fc * inv;

        out[OFF_PCA + (size_t)g * DD + tid] = pca;
        out[OFF_PX  + (size_t)g * DD + tid] = px;

        pv[0][tid] = pca; pv[1][tid] = pco; pv[2][tid] = px;
    }
    __syncthreads();

    if (tid < 3 * TT) {
        int v = tid / TT, tk = tid % TT;
        float acc = fcb[tk];
#pragma unroll 8
        for (int q = 0; q < DD; ++q) acc = fmaf(pv[v][q], wsh[tk * DD + q], acc);
        out[(size_t)v * (GG * TT) + g * TT + tk] = acc;
    }
}

extern "C" void kernel_launch(void* const* d_in, const int* in_sizes, int n_in,
                              void* d_out, int out_size) {
    const float* x        = (const float*)d_in[0];
    const int*   batch    = (const int*)  d_in[1];
    const float* codebook = (const float*)d_in[2];
    const float* causal   = (const float*)d_in[3];
    const float* counter  = (const float*)d_in[4];
    const float* fcw      = (const float*)d_in[5];
    const float* fcb      = (const float*)d_in[6];
    float* out = (float*)d_out;

    cudaFuncSetAttribute(argmin_tc,
                         cudaFuncAttributeMaxDynamicSharedMemorySize, SMEM_TC);

    setup_kernel<<<85, 256>>>(batch, causal);
    argmin_tc<<<NN / 128, 256, SMEM_TC>>>(x, codebook, out + OFF_Z);
    refine_kernel<<<592, 256>>>(x, codebook, out + OFF_Z);
    pool_kernel<<<GG, 256>>>(x, causal, counter, fcw, fcb, out);
}